// round 13
// baseline (speedup 1.0000x reference)
#include <cuda_runtime.h>
#include <cuda_fp16.h>
#include <mma.h>
#include <math.h>
#include <stdint.h>

using namespace nvcuda;

#define BATCH 4
#define SEQ   4096
#define DIMC  1024
#define NHEAD 16
#define HDIM  64
#define NWIN  16
#define BLKT  256
#define MTOK  (BATCH*SEQ)
#define ATTN_SCALE 0.125f

#define BM 128
#define BN 128
#define BKH 64
#define LDH 72           // half stride (144B rows, conflict-free LDSM)
#define NT  (DIMC / BKH)

// scratch (halves): xh, qh, kh, vh, goh (5 x 16M half) + 4 weights
__device__ __half g_scratch_h[5ull * MTOK * DIMC + 4ull * DIMC * DIMC];

// ---------------- helpers ----------------
__device__ __forceinline__ void cp_async16(void* smem, const void* gmem) {
    unsigned s = (unsigned)__cvta_generic_to_shared(smem);
    asm volatile("cp.async.cg.shared.global [%0], [%1], 16;\n" :: "r"(s), "l"(gmem));
}
__device__ __forceinline__ void cp_commit() {
    asm volatile("cp.async.commit_group;\n");
}
template<int N> __device__ __forceinline__ void cp_wait() {
    asm volatile("cp.async.wait_group %0;\n" :: "n"(N));
}
__device__ __forceinline__ float exp_poly(float v) {
    float t = v * 1.4426950408889634f;
    float fi = floorf(t);
    float f = t - fi;
    float p = 0.0001540353039338f;
    p = fmaf(p, f, 0.0013333558146428f);
    p = fmaf(p, f, 0.0096181291076285f);
    p = fmaf(p, f, 0.0555041086648216f);
    p = fmaf(p, f, 0.2402265069591007f);
    p = fmaf(p, f, 0.6931471805599453f);
    p = fmaf(p, f, 1.0f);
    int ei = (int)fi;
    ei = (ei < -126) ? -126 : ei;
    return p * __int_as_float((ei + 127) << 23);
}
__device__ __forceinline__ void ldsm_x4(uint32_t& r0, uint32_t& r1,
                                        uint32_t& r2, uint32_t& r3, uint32_t a) {
    asm volatile("ldmatrix.sync.aligned.m8n8.x4.shared.b16 {%0,%1,%2,%3}, [%4];"
                 : "=r"(r0), "=r"(r1), "=r"(r2), "=r"(r3) : "r"(a));
}
__device__ __forceinline__ void ldsm_x4_t(uint32_t& r0, uint32_t& r1,
                                          uint32_t& r2, uint32_t& r3, uint32_t a) {
    asm volatile("ldmatrix.sync.aligned.m8n8.x4.trans.shared.b16 {%0,%1,%2,%3}, [%4];"
                 : "=r"(r0), "=r"(r1), "=r"(r2), "=r"(r3) : "r"(a));
}
// mma with float4 accumulator — per-component constraints, no pointers.
__device__ __forceinline__ void mma_f4(float4& c,
                                       uint32_t a0, uint32_t a1, uint32_t a2, uint32_t a3,
                                       uint32_t b0, uint32_t b1) {
    asm volatile(
        "mma.sync.aligned.m16n8k16.row.col.f32.f16.f16.f32 "
        "{%0,%1,%2,%3}, {%4,%5,%6,%7}, {%8,%9}, {%0,%1,%2,%3};"
        : "+f"(c.x), "+f"(c.y), "+f"(c.z), "+f"(c.w)
        : "r"(a0), "r"(a1), "r"(a2), "r"(a3), "r"(b0), "r"(b1));
}

// no-op pad so the harness's fixed "-s 5 -c 1" ncu capture lands on attn
__global__ void pad_kernel() {}

// ---------------------------------------------------------------------------
// f32 -> f16 conversion prepass
// ---------------------------------------------------------------------------
__global__ void conv_half_kernel(
    const float4* __restrict__ x,  __half* __restrict__ xh,
    const float4* __restrict__ w0, __half* __restrict__ w0h,
    const float4* __restrict__ w1, __half* __restrict__ w1h,
    const float4* __restrict__ w2, __half* __restrict__ w2h,
    const float4* __restrict__ w3, __half* __restrict__ w3h)
{
    const float4* src; __half* dst; int n4;
    switch (blockIdx.z) {
        case 0:  src = x;  dst = xh;  n4 = MTOK * DIMC / 4; break;
        case 1:  src = w0; dst = w0h; n4 = DIMC * DIMC / 4; break;
        case 2:  src = w1; dst = w1h; n4 = DIMC * DIMC / 4; break;
        case 3:  src = w2; dst = w2h; n4 = DIMC * DIMC / 4; break;
        default: src = w3; dst = w3h; n4 = DIMC * DIMC / 4; break;
    }
    for (int i = blockIdx.x * blockDim.x + threadIdx.x; i < n4;
         i += gridDim.x * blockDim.x) {
        float4 v = src[i];
        __half2 a = __floats2half2_rn(v.x, v.y);
        __half2 b = __floats2half2_rn(v.z, v.w);
        uint2 o;
        o.x = *(const unsigned*)&a;
        o.y = *(const unsigned*)&b;
        *(uint2*)(dst + 4ull * i) = o;
    }
}

// ---------------------------------------------------------------------------
// fp16 GEMM (unchanged best)
// ---------------------------------------------------------------------------
__global__ __launch_bounds__(128, 3) void gemm3_f16(
    const __half* __restrict__ A,
    const __half* __restrict__ W0, const float* __restrict__ b0, void* __restrict__ C0,
    const __half* __restrict__ W1, const float* __restrict__ b1, void* __restrict__ C1,
    const __half* __restrict__ W2, const float* __restrict__ b2, void* __restrict__ C2,
    int halfOut)
{
    extern __shared__ __half smh[];
    const __half* Bw; const float* bias; void* C;
    if (blockIdx.z == 0)      { Bw = W0; bias = b0; C = C0; }
    else if (blockIdx.z == 1) { Bw = W1; bias = b1; C = C1; }
    else                      { Bw = W2; bias = b2; C = C2; }

    const int K = DIMC, N = DIMC;
    const int tid  = threadIdx.x;
    const int warp = tid >> 5;
    const int lane = tid & 31;
    const int wm = warp & 1;
    const int wn = warp >> 1;
    const int rowBase = blockIdx.y * BM;
    const int colBase = blockIdx.x * BN;

    const int stageH = BM * LDH;
    auto As = [&](int s) { return smh + (size_t)s * 2 * stageH; };
    auto Bs = [&](int s) { return smh + (size_t)s * 2 * stageH + stageH; };

    const int lr = tid >> 3;
    const int lc = (tid & 7) * 8;

    auto loadStage = [&](int s, int kt) {
        __half* as = As(s); __half* bs = Bs(s);
        int k0 = kt * BKH;
        #pragma unroll
        for (int j = 0; j < 8; j++) {
            int r = lr + j * 16;
            cp_async16(&as[r * LDH + lc], &A [(size_t)(rowBase + r) * K + k0 + lc]);
            cp_async16(&bs[r * LDH + lc], &Bw[(size_t)(colBase + r) * K + k0 + lc]);
        }
        cp_commit();
    };

    wmma::fragment<wmma::accumulator,16,16,16,float> acc[4][4];
    #pragma unroll
    for (int i = 0; i < 4; i++)
        #pragma unroll
        for (int j = 0; j < 4; j++)
            wmma::fill_fragment(acc[i][j], 0.0f);

    loadStage(0, 0);

    for (int kt = 0; kt < NT; kt++) {
        cp_wait<0>();
        __syncthreads();
        if (kt + 1 < NT) loadStage((kt + 1) & 1, kt + 1);

        const __half* as = As(kt & 1);
        const __half* bs = Bs(kt & 1);
        #pragma unroll
        for (int kk = 0; kk < BKH; kk += 16) {
            wmma::fragment<wmma::matrix_b,16,16,16,__half,wmma::col_major> bf[4];
            #pragma unroll
            for (int j = 0; j < 4; j++)
                wmma::load_matrix_sync(bf[j], bs + (wn*64 + j*16) * LDH + kk, LDH);
            #pragma unroll
            for (int i = 0; i < 4; i++) {
                wmma::fragment<wmma::matrix_a,16,16,16,__half,wmma::row_major> af;
                wmma::load_matrix_sync(af, as + (wm*64 + i*16) * LDH + kk, LDH);
                #pragma unroll
                for (int j = 0; j < 4; j++)
                    wmma::mma_sync(acc[i][j], af, bf[j], acc[i][j]);
            }
        }
    }
    __syncthreads();

    float* wstg = (float*)smh + warp * 352;
    #pragma unroll
    for (int i = 0; i < 4; i++) {
        #pragma unroll
        for (int j = 0; j < 4; j++) {
            wmma::store_matrix_sync(wstg, acc[i][j], 20, wmma::mem_row_major);
            __syncwarp();
            int r0 = rowBase + wm*64 + i*16;
            int c0 = colBase + wn*64 + j*16;
            int r  = lane >> 1;
            int cc = (lane & 1) * 8;
            float o[8];
            #pragma unroll
            for (int t = 0; t < 8; t++)
                o[t] = wstg[r*20 + cc + t] + __ldg(&bias[c0 + cc + t]);
            if (halfOut) {
                __half h[8];
                #pragma unroll
                for (int t = 0; t < 8; t++) h[t] = __float2half_rn(o[t]);
                *(uint4*)&((__half*)C)[(size_t)(r0 + r) * N + c0 + cc] = *(uint4*)h;
            } else {
                *(float4*)&((float*)C)[(size_t)(r0 + r) * N + c0 + cc]     = *(float4*)&o[0];
                *(float4*)&((float*)C)[(size_t)(r0 + r) * N + c0 + cc + 4] = *(float4*)&o[4];
            }
            __syncwarp();
        }
    }
}

// ---------------------------------------------------------------------------
// Attention v3 (fixed): fully register-resident, P never in smem.
// PV loop: 16 k-blocks (16 tokens each); block kb uses P tiles 2kb, 2kb+1.
// smem: Ks 36864 | Vs 36864 | Qs 18432 = 92160 bytes
// ---------------------------------------------------------------------------
#define ATTN_SMEM3 92160

__global__ __launch_bounds__(256, 1) void attn_kernel(
    const __half* __restrict__ q, const __half* __restrict__ k,
    const __half* __restrict__ v, __half* __restrict__ o,
    float* __restrict__ attnp)
{
    extern __shared__ char smraw[];
    __half* Ks = (__half*)smraw;
    __half* Vs = (__half*)(smraw + 36864);
    __half* Qs = (__half*)(smraw + 73728);

    const int tid  = threadIdx.x;
    const int warp = tid >> 5;
    const int lane = tid & 31;
    const int g    = lane >> 2;
    const int tg   = lane & 3;

    const int idx = blockIdx.x;
    const int qh  = idx & 1;
    const int bhw = idx >> 1;
    const int w = bhw & 15;
    const int h = (bhw >> 4) & 15;
    const int b = bhw >> 8;

    const size_t tokBase = (size_t)b * SEQ + (size_t)w * BLKT;
    const int    colBase = h * HDIM;
    const int    qrow0   = qh * 128;

    const __half* Kg = k + tokBase * DIMC + colBase;
    const __half* Vg = v + tokBase * DIMC + colBase;
    const __half* Qg = q + (tokBase + qrow0) * DIMC + colBase;

    #pragma unroll
    for (int j = 0; j < 8; j++) {
        int i = tid + j * 256;
        int r = i >> 3, u = (i & 7) * 8;
        cp_async16(&Ks[r*LDH + u], Kg + (size_t)r * DIMC + u);
        cp_async16(&Vs[r*LDH + u], Vg + (size_t)r * DIMC + u);
    }
    #pragma unroll
    for (int j = 0; j < 4; j++) {
        int i = tid + j * 256;
        int r = i >> 3, u = (i & 7) * 8;
        cp_async16(&Qs[r*LDH + u], Qg + (size_t)r * DIMC + u);
    }
    cp_commit();
    cp_wait<0>();
    __syncthreads();          // only CTA barrier

    // ---- A fragments (Q): warp's 16 rows, 4 k-tiles ----
    uint32_t qbase = (uint32_t)__cvta_generic_to_shared(Qs)
                   + ((warp*16 + (lane & 15)) * LDH + ((lane & 16) ? 8 : 0)) * 2;
    uint32_t Af0[4], Af1[4], Af2[4], Af3[4];
    ldsm_x4(Af0[0], Af0[1], Af0[2], Af0[3], qbase);
    ldsm_x4(Af1[0], Af1[1], Af1[2], Af1[3], qbase + 32);
    ldsm_x4(Af2[0], Af2[1], Af2[2], Af2[3], qbase + 64);
    ldsm_x4(Af3[0], Af3[1], Af3[2], Af3[3], qbase + 96);

    // ---- S = Q @ K^T : 32 n-tiles ----
    float4 acc[32];
    #pragma unroll
    for (int j = 0; j < 32; j++) acc[j] = make_float4(0.f, 0.f, 0.f, 0.f);

    uint32_t kbase = (uint32_t)__cvta_generic_to_shared(Ks)
                   + (((lane & 7) + ((lane & 16) ? 8 : 0)) * LDH
                      + ((lane & 8) ? 8 : 0)) * 2;
    #pragma unroll
    for (int j2 = 0; j2 < 16; j2++) {
        uint32_t kb = kbase + j2 * 16 * LDH * 2;
        uint32_t b0, b1, b2, b3;
        ldsm_x4(b0, b1, b2, b3, kb);
        mma_f4(acc[2*j2],   Af0[0], Af0[1], Af0[2], Af0[3], b0, b1);
        mma_f4(acc[2*j2+1], Af0[0], Af0[1], Af0[2], Af0[3], b2, b3);
        ldsm_x4(b0, b1, b2, b3, kb + 32);
        mma_f4(acc[2*j2],   Af1[0], Af1[1], Af1[2], Af1[3], b0, b1);
        mma_f4(acc[2*j2+1], Af1[0], Af1[1], Af1[2], Af1[3], b2, b3);
        ldsm_x4(b0, b1, b2, b3, kb + 64);
        mma_f4(acc[2*j2],   Af2[0], Af2[1], Af2[2], Af2[3], b0, b1);
        mma_f4(acc[2*j2+1], Af2[0], Af2[1], Af2[2], Af2[3], b2, b3);
        ldsm_x4(b0, b1, b2, b3, kb + 96);
        mma_f4(acc[2*j2],   Af3[0], Af3[1], Af3[2], Af3[3], b0, b1);
        mma_f4(acc[2*j2+1], Af3[0], Af3[1], Af3[2], Af3[3], b2, b3);
    }

    // ---- register softmax (rows g, g+8) ----
    float mx0 = -1e30f, mx1 = -1e30f;
    #pragma unroll
    for (int j = 0; j < 32; j++) {
        mx0 = fmaxf(mx0, fmaxf(acc[j].x, acc[j].y));
        mx1 = fmaxf(mx1, fmaxf(acc[j].z, acc[j].w));
    }
    mx0 = fmaxf(mx0, __shfl_xor_sync(0xffffffffu, mx0, 1));
    mx0 = fmaxf(mx0, __shfl_xor_sync(0xffffffffu, mx0, 2));
    mx1 = fmaxf(mx1, __shfl_xor_sync(0xffffffffu, mx1, 1));
    mx1 = fmaxf(mx1, __shfl_xor_sync(0xffffffffu, mx1, 2));

    float sum0 = 0.0f, sum1 = 0.0f;
    #pragma unroll
    for (int j = 0; j < 32; j++) {
        float e0, e1, e2, e3;
        if (j & 1) {
            e0 = exp_poly((acc[j].x - mx0) * ATTN_SCALE);
            e1 = exp_poly((acc[j].y - mx0) * ATTN_SCALE);
            e2 = exp_poly((acc[j].z - mx1) * ATTN_SCALE);
            e3 = exp_poly((acc[j].w - mx1) * ATTN_SCALE);
        } else {
            e0 = __expf((acc[j].x - mx0) * ATTN_SCALE);
            e1 = __expf((acc[j].y - mx0) * ATTN_SCALE);
            e2 = __expf((acc[j].z - mx1) * ATTN_SCALE);
            e3 = __expf((acc[j].w - mx1) * ATTN_SCALE);
        }
        acc[j].x = e0; acc[j].y = e1; acc[j].z = e2; acc[j].w = e3;
        sum0 += e0 + e1;
        sum1 += e2 + e3;
    }
    sum0 += __shfl_xor_sync(0xffffffffu, sum0, 1);
    sum0 += __shfl_xor_sync(0xffffffffu, sum0, 2);
    sum1 += __shfl_xor_sync(0xffffffffu, sum1, 1);
    sum1 += __shfl_xor_sync(0xffffffffu, sum1, 2);
    const float inv0 = 1.0f / sum0;
    const float inv1 = 1.0f / sum1;

    // ---- normalize, write attn from regs, pack P as half2 A-fragments ----
    uint32_t ph0[32], ph1[32];
    {
        const int lrow0 = warp*16 + g;
        float* a0 = attnp + ((((size_t)b*NHEAD + h)*NWIN + w)*BLKT
                             + qrow0 + lrow0) * BLKT + tg*2;
        float* a1 = a0 + 8 * BLKT;
        #pragma unroll
        for (int j = 0; j < 32; j++) {
            float v0 = acc[j].x * inv0, v1 = acc[j].y * inv0;
            float v2 = acc[j].z * inv1, v3 = acc[j].w * inv1;
            float2 f0 = {v0, v1}, f1 = {v2, v3};
            __stcs((float2*)(a0 + j*8), f0);
            __stcs((float2*)(a1 + j*8), f1);
            __half2 h0 = __floats2half2_rn(v0, v1);
            __half2 h1 = __floats2half2_rn(v2, v3);
            ph0[j] = *(const uint32_t*)&h0;
            ph1[j] = *(const uint32_t*)&h1;
        }
    }

    // ---- O = P @ V : 16 k-blocks; block kb uses P tiles 2kb, 2kb+1 ----
    float4 oacc[8];
    #pragma unroll
    for (int t = 0; t < 8; t++) oacc[t] = make_float4(0.f, 0.f, 0.f, 0.f);

    uint32_t vrow = ((lane >> 3) & 1) * 8 + (lane & 7);
    uint32_t vcolh = (lane >> 4) * 8;
    uint32_t vbase = (uint32_t)__cvta_generic_to_shared(Vs)
                   + (vrow * LDH + vcolh) * 2;
    #pragma unroll
    for (int kb = 0; kb < 16; kb++) {
        uint32_t va = vbase + (uint32_t)(kb * 16) * LDH * 2;
        uint32_t pa0 = ph0[2*kb],   pa1 = ph1[2*kb];
        uint32_t pa2 = ph0[2*kb+1], pa3 = ph1[2*kb+1];
        #pragma unroll
        for (int tt = 0; tt < 4; tt++) {
            uint32_t b0, b1, b2, b3;
            ldsm_x4_t(b0, b1, b2, b3, va + tt * 32);
            mma_f4(oacc[2*tt],   pa0, pa1, pa2, pa3, b0, b1);
            mma_f4(oacc[2*tt+1], pa0, pa1, pa2, pa3, b2, b3);
        }
    }

    // ---- store O directly as half2 ----
    {
        __half* orow0 = o + (tokBase + qrow0 + warp*16 + g) * DIMC + colBase + tg*2;
        __half* orow1 = orow0 + 8 * DIMC;
        #pragma unroll
        for (int t = 0; t < 8; t++) {
            __half2 h0 = __floats2half2_rn(oacc[t].x, oacc[t].y);
            __half2 h1 = __floats2half2_rn(oacc[t].z, oacc[t].w);
            *(__half2*)(orow0 + t*8) = h0;
            *(__half2*)(orow1 + t*8) = h1;
        }
    }
}

// ---------------------------------------------------------------------------
extern "C" void kernel_launch(void* const* d_in, const int* in_sizes, int n_in,
                              void* d_out, int out_size)
{
    const float* x  = (const float*)d_in[0];
    const float* Wq = (const float*)d_in[1];
    const float* bq = (const float*)d_in[2];
    const float* Wk = (const float*)d_in[3];
    const float* bk = (const float*)d_in[4];
    const float* Wv = (const float*)d_in[5];
    const float* bv = (const float*)d_in[6];
    const float* Wo = (const float*)d_in[7];
    const float* bo = (const float*)d_in[8];

    float* out = (float*)d_out;
    const size_t out_elems = (size_t)MTOK * DIMC;
    float* attnp = out + out_elems;

    __half* scratch = nullptr;
    cudaGetSymbolAddress((void**)&scratch, g_scratch_h);
    __half* xh  = scratch;
    __half* qh  = xh  + out_elems;
    __half* kh  = qh  + out_elems;
    __half* vh  = kh  + out_elems;
    __half* goh = vh  + out_elems;
    __half* wh  = goh + out_elems;
    const size_t wsz = (size_t)DIMC * DIMC;
    __half* whq = wh;
    __half* whk = wh + wsz;
    __half* whv = wh + 2*wsz;
    __half* who = wh + 3*wsz;

    // 3 pads -> ncu (-s 5 -c 1) captures attn
    pad_kernel<<<1, 32>>>();
    pad_kernel<<<1, 32>>>();
    pad_kernel<<<1, 32>>>();

    {
        dim3 rg(256, 1, 5);
        conv_half_kernel<<<rg, 256>>>(
            (const float4*)x,  xh,
            (const float4*)Wq, whq,
            (const float4*)Wk, whk,
            (const float4*)Wv, whv,
            (const float4*)Wo, who);
    }

    const size_t gemm_smem = 2ull * 2 * BM * LDH * sizeof(__half);  // 73728
    cudaFuncSetAttribute(gemm3_f16, cudaFuncAttributeMaxDynamicSharedMemorySize, (int)gemm_smem);

    dim3 gg(DIMC / BN, MTOK / BM, 3);
    gemm3_f16<<<gg, 128, gemm_smem>>>(xh, whq, bq, qh, whk, bk, kh, whv, bv, vh, 1);

    cudaFuncSetAttribute(attn_kernel, cudaFuncAttributeMaxDynamicSharedMemorySize, ATTN_SMEM3);
    attn_kernel<<<BATCH*NHEAD*NWIN*2, 256, ATTN_SMEM3>>>(qh, kh, vh, goh, attnp);

    dim3 go_grid(DIMC / BN, MTOK / BM, 1);
    gemm3_f16<<<go_grid, 128, gemm_smem>>>(goh, who, bo, out, who, bo, out, who, bo, out, 0);
}

// round 14
// speedup vs baseline: 1.0471x; 1.0471x over previous
#include <cuda_runtime.h>
#include <cuda_fp16.h>
#include <mma.h>
#include <math.h>
#include <stdint.h>

using namespace nvcuda;

#define BATCH 4
#define SEQ   4096
#define DIMC  1024
#define NHEAD 16
#define HDIM  64
#define NWIN  16
#define BLKT  256
#define MTOK  (BATCH*SEQ)
#define ATTN_SCALE 0.125f

#define BM 128
#define BN 128
#define BKH 64
#define LDH 72           // half stride (144B rows, conflict-free LDSM)
#define NT  (DIMC / BKH)
#define PLD 264          // P strip stride in halves (132 words: r*4 mod 32 distinct)

// scratch (halves): xh, qh, kh, vh, goh (5 x 16M half) + 4 weights
__device__ __half g_scratch_h[5ull * MTOK * DIMC + 4ull * DIMC * DIMC];

// ---------------- helpers ----------------
__device__ __forceinline__ void cp_async16(void* smem, const void* gmem) {
    unsigned s = (unsigned)__cvta_generic_to_shared(smem);
    asm volatile("cp.async.cg.shared.global [%0], [%1], 16;\n" :: "r"(s), "l"(gmem));
}
__device__ __forceinline__ void cp_commit() {
    asm volatile("cp.async.commit_group;\n");
}
template<int N> __device__ __forceinline__ void cp_wait() {
    asm volatile("cp.async.wait_group %0;\n" :: "n"(N));
}
__device__ __forceinline__ float exp_poly(float v) {
    float t = v * 1.4426950408889634f;
    float fi = floorf(t);
    float f = t - fi;
    float p = 0.0001540353039338f;
    p = fmaf(p, f, 0.0013333558146428f);
    p = fmaf(p, f, 0.0096181291076285f);
    p = fmaf(p, f, 0.0555041086648216f);
    p = fmaf(p, f, 0.2402265069591007f);
    p = fmaf(p, f, 0.6931471805599453f);
    p = fmaf(p, f, 1.0f);
    int ei = (int)fi;
    ei = (ei < -126) ? -126 : ei;
    return p * __int_as_float((ei + 127) << 23);
}
__device__ __forceinline__ void ldsm_x4(uint32_t& r0, uint32_t& r1,
                                        uint32_t& r2, uint32_t& r3, uint32_t a) {
    asm volatile("ldmatrix.sync.aligned.m8n8.x4.shared.b16 {%0,%1,%2,%3}, [%4];"
                 : "=r"(r0), "=r"(r1), "=r"(r2), "=r"(r3) : "r"(a));
}
__device__ __forceinline__ void ldsm_x4_t(uint32_t& r0, uint32_t& r1,
                                          uint32_t& r2, uint32_t& r3, uint32_t a) {
    asm volatile("ldmatrix.sync.aligned.m8n8.x4.trans.shared.b16 {%0,%1,%2,%3}, [%4];"
                 : "=r"(r0), "=r"(r1), "=r"(r2), "=r"(r3) : "r"(a));
}
__device__ __forceinline__ void mma_f4(float4& c,
                                       uint32_t a0, uint32_t a1, uint32_t a2, uint32_t a3,
                                       uint32_t b0, uint32_t b1) {
    asm volatile(
        "mma.sync.aligned.m16n8k16.row.col.f32.f16.f16.f32 "
        "{%0,%1,%2,%3}, {%4,%5,%6,%7}, {%8,%9}, {%0,%1,%2,%3};"
        : "+f"(c.x), "+f"(c.y), "+f"(c.z), "+f"(c.w)
        : "r"(a0), "r"(a1), "r"(a2), "r"(a3), "r"(b0), "r"(b1));
}

// ---------------------------------------------------------------------------
// f32 -> f16 conversion prepass
// ---------------------------------------------------------------------------
__global__ void conv_half_kernel(
    const float4* __restrict__ x,  __half* __restrict__ xh,
    const float4* __restrict__ w0, __half* __restrict__ w0h,
    const float4* __restrict__ w1, __half* __restrict__ w1h,
    const float4* __restrict__ w2, __half* __restrict__ w2h,
    const float4* __restrict__ w3, __half* __restrict__ w3h)
{
    const float4* src; __half* dst; int n4;
    switch (blockIdx.z) {
        case 0:  src = x;  dst = xh;  n4 = MTOK * DIMC / 4; break;
        case 1:  src = w0; dst = w0h; n4 = DIMC * DIMC / 4; break;
        case 2:  src = w1; dst = w1h; n4 = DIMC * DIMC / 4; break;
        case 3:  src = w2; dst = w2h; n4 = DIMC * DIMC / 4; break;
        default: src = w3; dst = w3h; n4 = DIMC * DIMC / 4; break;
    }
    for (int i = blockIdx.x * blockDim.x + threadIdx.x; i < n4;
         i += gridDim.x * blockDim.x) {
        float4 v = src[i];
        __half2 a = __floats2half2_rn(v.x, v.y);
        __half2 b = __floats2half2_rn(v.z, v.w);
        uint2 o;
        o.x = *(const unsigned*)&a;
        o.y = *(const unsigned*)&b;
        *(uint2*)(dst + 4ull * i) = o;
    }
}

// ---------------------------------------------------------------------------
// fp16 GEMM (unchanged best)
// ---------------------------------------------------------------------------
__global__ __launch_bounds__(128, 3) void gemm3_f16(
    const __half* __restrict__ A,
    const __half* __restrict__ W0, const float* __restrict__ b0, void* __restrict__ C0,
    const __half* __restrict__ W1, const float* __restrict__ b1, void* __restrict__ C1,
    const __half* __restrict__ W2, const float* __restrict__ b2, void* __restrict__ C2,
    int halfOut)
{
    extern __shared__ __half smh[];
    const __half* Bw; const float* bias; void* C;
    if (blockIdx.z == 0)      { Bw = W0; bias = b0; C = C0; }
    else if (blockIdx.z == 1) { Bw = W1; bias = b1; C = C1; }
    else                      { Bw = W2; bias = b2; C = C2; }

    const int K = DIMC, N = DIMC;
    const int tid  = threadIdx.x;
    const int warp = tid >> 5;
    const int lane = tid & 31;
    const int wm = warp & 1;
    const int wn = warp >> 1;
    const int rowBase = blockIdx.y * BM;
    const int colBase = blockIdx.x * BN;

    const int stageH = BM * LDH;
    auto As = [&](int s) { return smh + (size_t)s * 2 * stageH; };
    auto Bs = [&](int s) { return smh + (size_t)s * 2 * stageH + stageH; };

    const int lr = tid >> 3;
    const int lc = (tid & 7) * 8;

    auto loadStage = [&](int s, int kt) {
        __half* as = As(s); __half* bs = Bs(s);
        int k0 = kt * BKH;
        #pragma unroll
        for (int j = 0; j < 8; j++) {
            int r = lr + j * 16;
            cp_async16(&as[r * LDH + lc], &A [(size_t)(rowBase + r) * K + k0 + lc]);
            cp_async16(&bs[r * LDH + lc], &Bw[(size_t)(colBase + r) * K + k0 + lc]);
        }
        cp_commit();
    };

    wmma::fragment<wmma::accumulator,16,16,16,float> acc[4][4];
    #pragma unroll
    for (int i = 0; i < 4; i++)
        #pragma unroll
        for (int j = 0; j < 4; j++)
            wmma::fill_fragment(acc[i][j], 0.0f);

    loadStage(0, 0);

    for (int kt = 0; kt < NT; kt++) {
        cp_wait<0>();
        __syncthreads();
        if (kt + 1 < NT) loadStage((kt + 1) & 1, kt + 1);

        const __half* as = As(kt & 1);
        const __half* bs = Bs(kt & 1);
        #pragma unroll
        for (int kk = 0; kk < BKH; kk += 16) {
            wmma::fragment<wmma::matrix_b,16,16,16,__half,wmma::col_major> bf[4];
            #pragma unroll
            for (int j = 0; j < 4; j++)
                wmma::load_matrix_sync(bf[j], bs + (wn*64 + j*16) * LDH + kk, LDH);
            #pragma unroll
            for (int i = 0; i < 4; i++) {
                wmma::fragment<wmma::matrix_a,16,16,16,__half,wmma::row_major> af;
                wmma::load_matrix_sync(af, as + (wm*64 + i*16) * LDH + kk, LDH);
                #pragma unroll
                for (int j = 0; j < 4; j++)
                    wmma::mma_sync(acc[i][j], af, bf[j], acc[i][j]);
            }
        }
    }
    __syncthreads();

    float* wstg = (float*)smh + warp * 352;
    #pragma unroll
    for (int i = 0; i < 4; i++) {
        #pragma unroll
        for (int j = 0; j < 4; j++) {
            wmma::store_matrix_sync(wstg, acc[i][j], 20, wmma::mem_row_major);
            __syncwarp();
            int r0 = rowBase + wm*64 + i*16;
            int c0 = colBase + wn*64 + j*16;
            int r  = lane >> 1;
            int cc = (lane & 1) * 8;
            float o[8];
            #pragma unroll
            for (int t = 0; t < 8; t++)
                o[t] = wstg[r*20 + cc + t] + __ldg(&bias[c0 + cc + t]);
            if (halfOut) {
                __half h[8];
                #pragma unroll
                for (int t = 0; t < 8; t++) h[t] = __float2half_rn(o[t]);
                *(uint4*)&((__half*)C)[(size_t)(r0 + r) * N + c0 + cc] = *(uint4*)h;
            } else {
                *(float4*)&((float*)C)[(size_t)(r0 + r) * N + c0 + cc]     = *(float4*)&o[0];
                *(float4*)&((float*)C)[(size_t)(r0 + r) * N + c0 + cc + 4] = *(float4*)&o[4];
            }
            __syncwarp();
        }
    }
}

// ---------------------------------------------------------------------------
// Attention v4: 64 q-rows per CTA (4 warps, 128 threads), 2 CTAs/SM.
// Register softmax (no spills: P staged through smem aliased onto Ks after a
// sync, so peak regs ~= S(128)+Af(16)+addr). 4 CTAs/window, adjacent
// blockIdx -> K/V re-reads served by L2. Verified fragment mappings from R13.
// smem: Ks/Ps 36864 | Vs 36864 | Qs 9216 = 82944 bytes
// ---------------------------------------------------------------------------
#define ATTN_SMEM4 82944

__global__ __launch_bounds__(128, 2) void attn_kernel(
    const __half* __restrict__ q, const __half* __restrict__ k,
    const __half* __restrict__ v, __half* __restrict__ o,
    float* __restrict__ attnp)
{
    extern __shared__ char smraw[];
    __half* Ks = (__half*)smraw;                 // later aliased as Ps
    __half* Vs = (__half*)(smraw + 36864);
    __half* Qs = (__half*)(smraw + 73728);
    __half* Ps = Ks;

    const int tid  = threadIdx.x;
    const int warp = tid >> 5;
    const int lane = tid & 31;
    const int g    = lane >> 2;
    const int tg   = lane & 3;

    const int idx  = blockIdx.x;
    const int part = idx & 3;                    // 64-row chunk
    const int bhw  = idx >> 2;
    const int w = bhw & 15;
    const int h = (bhw >> 4) & 15;
    const int b = bhw >> 8;

    const size_t tokBase = (size_t)b * SEQ + (size_t)w * BLKT;
    const int    colBase = h * HDIM;
    const int    qrow0   = part * 64;

    const __half* Kg = k + tokBase * DIMC + colBase;
    const __half* Vg = v + tokBase * DIMC + colBase;
    const __half* Qg = q + (tokBase + qrow0) * DIMC + colBase;

    // K,V: 2048 16B-chunks each; Q: 512 chunks. 128 threads.
    #pragma unroll
    for (int j = 0; j < 16; j++) {
        int i = tid + j * 128;
        int r = i >> 3, u = (i & 7) * 8;
        cp_async16(&Ks[r*LDH + u], Kg + (size_t)r * DIMC + u);
        cp_async16(&Vs[r*LDH + u], Vg + (size_t)r * DIMC + u);
    }
    #pragma unroll
    for (int j = 0; j < 4; j++) {
        int i = tid + j * 128;
        int r = i >> 3, u = (i & 7) * 8;
        cp_async16(&Qs[r*LDH + u], Qg + (size_t)r * DIMC + u);
    }
    cp_commit();
    cp_wait<0>();
    __syncthreads();

    // ---- A fragments (Q): warp's 16 rows, 4 k-tiles ----
    uint32_t qbase = (uint32_t)__cvta_generic_to_shared(Qs)
                   + ((warp*16 + (lane & 15)) * LDH + ((lane & 16) ? 8 : 0)) * 2;
    uint32_t Af0[4], Af1[4], Af2[4], Af3[4];
    ldsm_x4(Af0[0], Af0[1], Af0[2], Af0[3], qbase);
    ldsm_x4(Af1[0], Af1[1], Af1[2], Af1[3], qbase + 32);
    ldsm_x4(Af2[0], Af2[1], Af2[2], Af2[3], qbase + 64);
    ldsm_x4(Af3[0], Af3[1], Af3[2], Af3[3], qbase + 96);

    // ---- S = Q @ K^T : 32 n-tiles ----
    float4 acc[32];
    #pragma unroll
    for (int j = 0; j < 32; j++) acc[j] = make_float4(0.f, 0.f, 0.f, 0.f);

    uint32_t kbase = (uint32_t)__cvta_generic_to_shared(Ks)
                   + (((lane & 7) + ((lane & 16) ? 8 : 0)) * LDH
                      + ((lane & 8) ? 8 : 0)) * 2;
    #pragma unroll
    for (int j2 = 0; j2 < 16; j2++) {
        uint32_t kb = kbase + j2 * 16 * LDH * 2;
        uint32_t b0, b1, b2, b3;
        ldsm_x4(b0, b1, b2, b3, kb);
        mma_f4(acc[2*j2],   Af0[0], Af0[1], Af0[2], Af0[3], b0, b1);
        mma_f4(acc[2*j2+1], Af0[0], Af0[1], Af0[2], Af0[3], b2, b3);
        ldsm_x4(b0, b1, b2, b3, kb + 32);
        mma_f4(acc[2*j2],   Af1[0], Af1[1], Af1[2], Af1[3], b0, b1);
        mma_f4(acc[2*j2+1], Af1[0], Af1[1], Af1[2], Af1[3], b2, b3);
        ldsm_x4(b0, b1, b2, b3, kb + 64);
        mma_f4(acc[2*j2],   Af2[0], Af2[1], Af2[2], Af2[3], b0, b1);
        mma_f4(acc[2*j2+1], Af2[0], Af2[1], Af2[2], Af2[3], b2, b3);
        ldsm_x4(b0, b1, b2, b3, kb + 96);
        mma_f4(acc[2*j2],   Af3[0], Af3[1], Af3[2], Af3[3], b0, b1);
        mma_f4(acc[2*j2+1], Af3[0], Af3[1], Af3[2], Af3[3], b2, b3);
    }

    // ---- register softmax (rows g, g+8 of warp strip) ----
    float mx0 = -1e30f, mx1 = -1e30f;
    #pragma unroll
    for (int j = 0; j < 32; j++) {
        mx0 = fmaxf(mx0, fmaxf(acc[j].x, acc[j].y));
        mx1 = fmaxf(mx1, fmaxf(acc[j].z, acc[j].w));
    }
    mx0 = fmaxf(mx0, __shfl_xor_sync(0xffffffffu, mx0, 1));
    mx0 = fmaxf(mx0, __shfl_xor_sync(0xffffffffu, mx0, 2));
    mx1 = fmaxf(mx1, __shfl_xor_sync(0xffffffffu, mx1, 1));
    mx1 = fmaxf(mx1, __shfl_xor_sync(0xffffffffu, mx1, 2));

    float sum0 = 0.0f, sum1 = 0.0f;
    #pragma unroll
    for (int j = 0; j < 32; j++) {
        float e0, e1, e2, e3;
        if (j & 1) {
            e0 = exp_poly((acc[j].x - mx0) * ATTN_SCALE);
            e1 = exp_poly((acc[j].y - mx0) * ATTN_SCALE);
            e2 = exp_poly((acc[j].z - mx1) * ATTN_SCALE);
            e3 = exp_poly((acc[j].w - mx1) * ATTN_SCALE);
        } else {
            e0 = __expf((acc[j].x - mx0) * ATTN_SCALE);
            e1 = __expf((acc[j].y - mx0) * ATTN_SCALE);
            e2 = __expf((acc[j].z - mx1) * ATTN_SCALE);
            e3 = __expf((acc[j].w - mx1) * ATTN_SCALE);
        }
        acc[j].x = e0; acc[j].y = e1; acc[j].z = e2; acc[j].w = e3;
        sum0 += e0 + e1;
        sum1 += e2 + e3;
    }
    sum0 += __shfl_xor_sync(0xffffffffu, sum0, 1);
    sum0 += __shfl_xor_sync(0xffffffffu, sum0, 2);
    sum1 += __shfl_xor_sync(0xffffffffu, sum1, 1);
    sum1 += __shfl_xor_sync(0xffffffffu, sum1, 2);
    const float inv0 = 1.0f / sum0;
    const float inv1 = 1.0f / sum1;

    // ---- normalize in regs, write attn from regs ----
    {
        const int lrow0 = warp*16 + g;
        float* a0 = attnp + ((((size_t)b*NHEAD + h)*NWIN + w)*BLKT
                             + qrow0 + lrow0) * BLKT + tg*2;
        float* a1 = a0 + 8 * BLKT;
        #pragma unroll
        for (int j = 0; j < 32; j++) {
            acc[j].x *= inv0; acc[j].y *= inv0;
            acc[j].z *= inv1; acc[j].w *= inv1;
            float2 f0 = {acc[j].x, acc[j].y};
            float2 f1 = {acc[j].z, acc[j].w};
            __stcs((float2*)(a0 + j*8), f0);
            __stcs((float2*)(a1 + j*8), f1);
        }
    }

    __syncthreads();          // all warps done reading Ks before Ps overwrite

    // ---- store P (fp16) into Ps (aliased on Ks) ----
    {
        __half* p0 = Ps + (size_t)(warp*16 + g) * PLD + tg*2;
        __half* p1 = p0 + 8 * PLD;
        #pragma unroll
        for (int j = 0; j < 32; j++) {
            *(__half2*)(p0 + j*8) = __floats2half2_rn(acc[j].x, acc[j].y);
            *(__half2*)(p1 + j*8) = __floats2half2_rn(acc[j].z, acc[j].w);
        }
    }
    __syncwarp();             // warp reads only its own strip

    // ---- O = P @ V : P via ldsm (same mapping as Q), V via ldsm.trans ----
    float4 oacc[8];
    #pragma unroll
    for (int t = 0; t < 8; t++) oacc[t] = make_float4(0.f, 0.f, 0.f, 0.f);

    uint32_t pbase = (uint32_t)__cvta_generic_to_shared(Ps)
                   + ((warp*16 + (lane & 15)) * PLD + ((lane & 16) ? 8 : 0)) * 2;
    uint32_t vrow = ((lane >> 3) & 1) * 8 + (lane & 7);
    uint32_t vcolh = (lane >> 4) * 8;
    uint32_t vbase = (uint32_t)__cvta_generic_to_shared(Vs)
                   + (vrow * LDH + vcolh) * 2;
    #pragma unroll
    for (int kb = 0; kb < 16; kb++) {
        uint32_t pa0, pa1, pa2, pa3;
        ldsm_x4(pa0, pa1, pa2, pa3, pbase + (uint32_t)kb * 32);
        uint32_t va = vbase + (uint32_t)(kb * 16) * LDH * 2;
        #pragma unroll
        for (int tt = 0; tt < 4; tt++) {
            uint32_t b0, b1, b2, b3;
            ldsm_x4_t(b0, b1, b2, b3, va + tt * 32);
            mma_f4(oacc[2*tt],   pa0, pa1, pa2, pa3, b0, b1);
            mma_f4(oacc[2*tt+1], pa0, pa1, pa2, pa3, b2, b3);
        }
    }

    // ---- store O directly as half2 ----
    {
        __half* orow0 = o + (tokBase + qrow0 + warp*16 + g) * DIMC + colBase + tg*2;
        __half* orow1 = orow0 + 8 * DIMC;
        #pragma unroll
        for (int t = 0; t < 8; t++) {
            *(__half2*)(orow0 + t*8) = __floats2half2_rn(oacc[t].x, oacc[t].y);
            *(__half2*)(orow1 + t*8) = __floats2half2_rn(oacc[t].z, oacc[t].w);
        }
    }
}

// ---------------------------------------------------------------------------
extern "C" void kernel_launch(void* const* d_in, const int* in_sizes, int n_in,
                              void* d_out, int out_size)
{
    const float* x  = (const float*)d_in[0];
    const float* Wq = (const float*)d_in[1];
    const float* bq = (const float*)d_in[2];
    const float* Wk = (const float*)d_in[3];
    const float* bk = (const float*)d_in[4];
    const float* Wv = (const float*)d_in[5];
    const float* bv = (const float*)d_in[6];
    const float* Wo = (const float*)d_in[7];
    const float* bo = (const float*)d_in[8];

    float* out = (float*)d_out;
    const size_t out_elems = (size_t)MTOK * DIMC;
    float* attnp = out + out_elems;

    __half* scratch = nullptr;
    cudaGetSymbolAddress((void**)&scratch, g_scratch_h);
    __half* xh  = scratch;
    __half* qh  = xh  + out_elems;
    __half* kh  = qh  + out_elems;
    __half* vh  = kh  + out_elems;
    __half* goh = vh  + out_elems;
    __half* wh  = goh + out_elems;
    const size_t wsz = (size_t)DIMC * DIMC;
    __half* whq = wh;
    __half* whk = wh + wsz;
    __half* whv = wh + 2*wsz;
    __half* who = wh + 3*wsz;

    {
        dim3 rg(256, 1, 5);
        conv_half_kernel<<<rg, 256>>>(
            (const float4*)x,  xh,
            (const float4*)Wq, whq,
            (const float4*)Wk, whk,
            (const float4*)Wv, whv,
            (const float4*)Wo, who);
    }

    const size_t gemm_smem = 2ull * 2 * BM * LDH * sizeof(__half);  // 73728
    cudaFuncSetAttribute(gemm3_f16, cudaFuncAttributeMaxDynamicSharedMemorySize, (int)gemm_smem);

    dim3 gg(DIMC / BN, MTOK / BM, 3);
    gemm3_f16<<<gg, 128, gemm_smem>>>(xh, whq, bq, qh, whk, bk, kh, whv, bv, vh, 1);

    cudaFuncSetAttribute(attn_kernel, cudaFuncAttributeMaxDynamicSharedMemorySize, ATTN_SMEM4);
    attn_kernel<<<BATCH*NHEAD*NWIN*4, 128, ATTN_SMEM4>>>(qh, kh, vh, goh, attnp);

    dim3 go_grid(DIMC / BN, MTOK / BM, 1);
    gemm3_f16<<<go_grid, 128, gemm_smem>>>(goh, who, bo, out, who, bo, out, who, bo, out, 0);
}

// round 15
// speedup vs baseline: 1.1090x; 1.0591x over previous
#include <cuda_runtime.h>
#include <cuda_fp16.h>
#include <math.h>
#include <stdint.h>

#define BATCH 4
#define SEQ   4096
#define DIMC  1024
#define NHEAD 16
#define HDIM  64
#define NWIN  16
#define BLKT  256
#define MTOK  (BATCH*SEQ)
#define ATTN_SCALE 0.125f

#define BM 128
#define BN 128
#define BKH 64
#define LDH 72           // half stride (144B rows, conflict-free LDSM)
#define NT  (DIMC / BKH)
#define PLD 264

// scratch (halves): xh, qh, kh, vh, goh (5 x 16M half) + 4 weights
__device__ __half g_scratch_h[5ull * MTOK * DIMC + 4ull * DIMC * DIMC];

// ---------------- helpers ----------------
__device__ __forceinline__ void cp_async16(void* smem, const void* gmem) {
    unsigned s = (unsigned)__cvta_generic_to_shared(smem);
    asm volatile("cp.async.cg.shared.global [%0], [%1], 16;\n" :: "r"(s), "l"(gmem));
}
__device__ __forceinline__ void cp_commit() {
    asm volatile("cp.async.commit_group;\n");
}
template<int N> __device__ __forceinline__ void cp_wait() {
    asm volatile("cp.async.wait_group %0;\n" :: "n"(N));
}
__device__ __forceinline__ float exp_poly(float v) {
    float t = v * 1.4426950408889634f;
    float fi = floorf(t);
    float f = t - fi;
    float p = 0.0001540353039338f;
    p = fmaf(p, f, 0.0013333558146428f);
    p = fmaf(p, f, 0.0096181291076285f);
    p = fmaf(p, f, 0.0555041086648216f);
    p = fmaf(p, f, 0.2402265069591007f);
    p = fmaf(p, f, 0.6931471805599453f);
    p = fmaf(p, f, 1.0f);
    int ei = (int)fi;
    ei = (ei < -126) ? -126 : ei;
    return p * __int_as_float((ei + 127) << 23);
}
__device__ __forceinline__ void ldsm_x4(uint32_t& r0, uint32_t& r1,
                                        uint32_t& r2, uint32_t& r3, uint32_t a) {
    asm volatile("ldmatrix.sync.aligned.m8n8.x4.shared.b16 {%0,%1,%2,%3}, [%4];"
                 : "=r"(r0), "=r"(r1), "=r"(r2), "=r"(r3) : "r"(a));
}
__device__ __forceinline__ void ldsm_x4_t(uint32_t& r0, uint32_t& r1,
                                          uint32_t& r2, uint32_t& r3, uint32_t a) {
    asm volatile("ldmatrix.sync.aligned.m8n8.x4.trans.shared.b16 {%0,%1,%2,%3}, [%4];"
                 : "=r"(r0), "=r"(r1), "=r"(r2), "=r"(r3) : "r"(a));
}
__device__ __forceinline__ void mma_f4(float4& c,
                                       uint32_t a0, uint32_t a1, uint32_t a2, uint32_t a3,
                                       uint32_t b0, uint32_t b1) {
    asm volatile(
        "mma.sync.aligned.m16n8k16.row.col.f32.f16.f16.f32 "
        "{%0,%1,%2,%3}, {%4,%5,%6,%7}, {%8,%9}, {%0,%1,%2,%3};"
        : "+f"(c.x), "+f"(c.y), "+f"(c.z), "+f"(c.w)
        : "r"(a0), "r"(a1), "r"(a2), "r"(a3), "r"(b0), "r"(b1));
}

// ---------------------------------------------------------------------------
// f32 -> f16 conversion prepass
// ---------------------------------------------------------------------------
__global__ void conv_half_kernel(
    const float4* __restrict__ x,  __half* __restrict__ xh,
    const float4* __restrict__ w0, __half* __restrict__ w0h,
    const float4* __restrict__ w1, __half* __restrict__ w1h,
    const float4* __restrict__ w2, __half* __restrict__ w2h,
    const float4* __restrict__ w3, __half* __restrict__ w3h)
{
    const float4* src; __half* dst; int n4;
    switch (blockIdx.z) {
        case 0:  src = x;  dst = xh;  n4 = MTOK * DIMC / 4; break;
        case 1:  src = w0; dst = w0h; n4 = DIMC * DIMC / 4; break;
        case 2:  src = w1; dst = w1h; n4 = DIMC * DIMC / 4; break;
        case 3:  src = w2; dst = w2h; n4 = DIMC * DIMC / 4; break;
        default: src = w3; dst = w3h; n4 = DIMC * DIMC / 4; break;
    }
    for (int i = blockIdx.x * blockDim.x + threadIdx.x; i < n4;
         i += gridDim.x * blockDim.x) {
        float4 v = src[i];
        __half2 a = __floats2half2_rn(v.x, v.y);
        __half2 b = __floats2half2_rn(v.z, v.w);
        uint2 o;
        o.x = *(const unsigned*)&a;
        o.y = *(const unsigned*)&b;
        *(uint2*)(dst + 4ull * i) = o;
    }
}

// ---------------------------------------------------------------------------
// fp16 GEMM v2: raw ldsm + mma (8 LDSM.x4 : 32 HMMA per kk, half the wmma
// LDSM traffic). 128x128 CTA tile, 4 warps (64x64 warp tile), BK=64, 2-stage
// cp.async wait-all pipeline, 3 CTAs/SM. Fragment mappings identical to the
// (correctness-proven) attention kernel. Epilogue writes straight from
// fragments with pre-loaded bias (no smem staging).
// ---------------------------------------------------------------------------
__global__ __launch_bounds__(128, 3) void gemm3_f16(
    const __half* __restrict__ A,
    const __half* __restrict__ W0, const float* __restrict__ b0, void* __restrict__ C0,
    const __half* __restrict__ W1, const float* __restrict__ b1, void* __restrict__ C1,
    const __half* __restrict__ W2, const float* __restrict__ b2, void* __restrict__ C2,
    int halfOut)
{
    extern __shared__ __half smh[];
    const __half* Bw; const float* bias; void* C;
    if (blockIdx.z == 0)      { Bw = W0; bias = b0; C = C0; }
    else if (blockIdx.z == 1) { Bw = W1; bias = b1; C = C1; }
    else                      { Bw = W2; bias = b2; C = C2; }

    const int K = DIMC, N = DIMC;
    const int tid  = threadIdx.x;
    const int warp = tid >> 5;
    const int lane = tid & 31;
    const int g    = lane >> 2;
    const int tg   = lane & 3;
    const int wm = warp & 1;
    const int wn = warp >> 1;
    const int rowBase = blockIdx.y * BM;
    const int colBase = blockIdx.x * BN;

    const int stageH = BM * LDH;
    auto As = [&](int s) { return smh + (size_t)s * 2 * stageH; };
    auto Bs = [&](int s) { return smh + (size_t)s * 2 * stageH + stageH; };

    const int lr = tid >> 3;
    const int lc = (tid & 7) * 8;

    auto loadStage = [&](int s, int kt) {
        __half* as = As(s); __half* bs = Bs(s);
        int k0 = kt * BKH;
        #pragma unroll
        for (int j = 0; j < 8; j++) {
            int r = lr + j * 16;
            cp_async16(&as[r * LDH + lc], &A [(size_t)(rowBase + r) * K + k0 + lc]);
            cp_async16(&bs[r * LDH + lc], &Bw[(size_t)(colBase + r) * K + k0 + lc]);
        }
        cp_commit();
    };

    // acc[i][t]: m-tile i (16 rows), n8-tile t (8 cols).
    float4 acc[4][8];
    #pragma unroll
    for (int i = 0; i < 4; i++)
        #pragma unroll
        for (int t = 0; t < 8; t++)
            acc[i][t] = make_float4(0.f, 0.f, 0.f, 0.f);

    loadStage(0, 0);

    // intra-tile fragment address offsets (bytes)
    const uint32_t aoff = ((uint32_t)(wm*64 + (lane & 15)) * LDH
                         + ((lane & 16) ? 8 : 0)) * 2;
    const uint32_t boff = ((uint32_t)(wn*64 + (lane & 7) + ((lane & 16) ? 8 : 0)) * LDH
                         + ((lane & 8) ? 8 : 0)) * 2;

    for (int kt = 0; kt < NT; kt++) {
        cp_wait<0>();
        __syncthreads();
        if (kt + 1 < NT) loadStage((kt + 1) & 1, kt + 1);

        uint32_t abase = (uint32_t)__cvta_generic_to_shared(As(kt & 1)) + aoff;
        uint32_t bbase = (uint32_t)__cvta_generic_to_shared(Bs(kt & 1)) + boff;
        #pragma unroll
        for (int kk = 0; kk < BKH; kk += 16) {
            uint32_t Bf[4][4];
            #pragma unroll
            for (int j = 0; j < 4; j++)
                ldsm_x4(Bf[j][0], Bf[j][1], Bf[j][2], Bf[j][3],
                        bbase + (uint32_t)(j*16) * LDH * 2 + kk*2);
            #pragma unroll
            for (int i = 0; i < 4; i++) {
                uint32_t a0, a1, a2, a3;
                ldsm_x4(a0, a1, a2, a3,
                        abase + (uint32_t)(i*16) * LDH * 2 + kk*2);
                #pragma unroll
                for (int j = 0; j < 4; j++) {
                    mma_f4(acc[i][2*j],   a0, a1, a2, a3, Bf[j][0], Bf[j][1]);
                    mma_f4(acc[i][2*j+1], a0, a1, a2, a3, Bf[j][2], Bf[j][3]);
                }
            }
        }
    }

    // epilogue: bias pre-load (16 values per thread), direct fragment stores
    float bv0[8], bv1[8];
    #pragma unroll
    for (int t = 0; t < 8; t++) {
        int col = colBase + wn*64 + t*8 + tg*2;
        bv0[t] = __ldg(&bias[col]);
        bv1[t] = __ldg(&bias[col + 1]);
    }
    #pragma unroll
    for (int i = 0; i < 4; i++) {
        int row0 = rowBase + wm*64 + i*16 + g;
        #pragma unroll
        for (int t = 0; t < 8; t++) {
            int col = colBase + wn*64 + t*8 + tg*2;
            float x0 = acc[i][t].x + bv0[t];
            float y0 = acc[i][t].y + bv1[t];
            float x1 = acc[i][t].z + bv0[t];
            float y1 = acc[i][t].w + bv1[t];
            if (halfOut) {
                __half* Ch = (__half*)C;
                *(__half2*)&Ch[(size_t)row0 * N + col]       = __floats2half2_rn(x0, y0);
                *(__half2*)&Ch[(size_t)(row0+8) * N + col]   = __floats2half2_rn(x1, y1);
            } else {
                float* Cf = (float*)C;
                float2 f0 = {x0, y0}, f1 = {x1, y1};
                *(float2*)&Cf[(size_t)row0 * N + col]     = f0;
                *(float2*)&Cf[(size_t)(row0+8) * N + col] = f1;
            }
        }
    }
}

// ---------------------------------------------------------------------------
// Attention v4 (unchanged from R14 best): 64 q-rows/CTA, 4 warps, 2 CTAs/SM,
// register softmax, P staged via smem aliased onto Ks.
// smem: Ks/Ps 36864 | Vs 36864 | Qs 9216 = 82944 bytes
// ---------------------------------------------------------------------------
#define ATTN_SMEM4 82944

__global__ __launch_bounds__(128, 2) void attn_kernel(
    const __half* __restrict__ q, const __half* __restrict__ k,
    const __half* __restrict__ v, __half* __restrict__ o,
    float* __restrict__ attnp)
{
    extern __shared__ char smraw[];
    __half* Ks = (__half*)smraw;
    __half* Vs = (__half*)(smraw + 36864);
    __half* Qs = (__half*)(smraw + 73728);
    __half* Ps = Ks;

    const int tid  = threadIdx.x;
    const int warp = tid >> 5;
    const int lane = tid & 31;
    const int g    = lane >> 2;
    const int tg   = lane & 3;

    const int idx  = blockIdx.x;
    const int part = idx & 3;
    const int bhw  = idx >> 2;
    const int w = bhw & 15;
    const int h = (bhw >> 4) & 15;
    const int b = bhw >> 8;

    const size_t tokBase = (size_t)b * SEQ + (size_t)w * BLKT;
    const int    colBase = h * HDIM;
    const int    qrow0   = part * 64;

    const __half* Kg = k + tokBase * DIMC + colBase;
    const __half* Vg = v + tokBase * DIMC + colBase;
    const __half* Qg = q + (tokBase + qrow0) * DIMC + colBase;

    #pragma unroll
    for (int j = 0; j < 16; j++) {
        int i = tid + j * 128;
        int r = i >> 3, u = (i & 7) * 8;
        cp_async16(&Ks[r*LDH + u], Kg + (size_t)r * DIMC + u);
        cp_async16(&Vs[r*LDH + u], Vg + (size_t)r * DIMC + u);
    }
    #pragma unroll
    for (int j = 0; j < 4; j++) {
        int i = tid + j * 128;
        int r = i >> 3, u = (i & 7) * 8;
        cp_async16(&Qs[r*LDH + u], Qg + (size_t)r * DIMC + u);
    }
    cp_commit();
    cp_wait<0>();
    __syncthreads();

    uint32_t qbase = (uint32_t)__cvta_generic_to_shared(Qs)
                   + ((warp*16 + (lane & 15)) * LDH + ((lane & 16) ? 8 : 0)) * 2;
    uint32_t Af0[4], Af1[4], Af2[4], Af3[4];
    ldsm_x4(Af0[0], Af0[1], Af0[2], Af0[3], qbase);
    ldsm_x4(Af1[0], Af1[1], Af1[2], Af1[3], qbase + 32);
    ldsm_x4(Af2[0], Af2[1], Af2[2], Af2[3], qbase + 64);
    ldsm_x4(Af3[0], Af3[1], Af3[2], Af3[3], qbase + 96);

    float4 acc[32];
    #pragma unroll
    for (int j = 0; j < 32; j++) acc[j] = make_float4(0.f, 0.f, 0.f, 0.f);

    uint32_t kbase = (uint32_t)__cvta_generic_to_shared(Ks)
                   + (((lane & 7) + ((lane & 16) ? 8 : 0)) * LDH
                      + ((lane & 8) ? 8 : 0)) * 2;
    #pragma unroll
    for (int j2 = 0; j2 < 16; j2++) {
        uint32_t kb = kbase + j2 * 16 * LDH * 2;
        uint32_t b0, b1, b2, b3;
        ldsm_x4(b0, b1, b2, b3, kb);
        mma_f4(acc[2*j2],   Af0[0], Af0[1], Af0[2], Af0[3], b0, b1);
        mma_f4(acc[2*j2+1], Af0[0], Af0[1], Af0[2], Af0[3], b2, b3);
        ldsm_x4(b0, b1, b2, b3, kb + 32);
        mma_f4(acc[2*j2],   Af1[0], Af1[1], Af1[2], Af1[3], b0, b1);
        mma_f4(acc[2*j2+1], Af1[0], Af1[1], Af1[2], Af1[3], b2, b3);
        ldsm_x4(b0, b1, b2, b3, kb + 64);
        mma_f4(acc[2*j2],   Af2[0], Af2[1], Af2[2], Af2[3], b0, b1);
        mma_f4(acc[2*j2+1], Af2[0], Af2[1], Af2[2], Af2[3], b2, b3);
        ldsm_x4(b0, b1, b2, b3, kb + 96);
        mma_f4(acc[2*j2],   Af3[0], Af3[1], Af3[2], Af3[3], b0, b1);
        mma_f4(acc[2*j2+1], Af3[0], Af3[1], Af3[2], Af3[3], b2, b3);
    }

    float mx0 = -1e30f, mx1 = -1e30f;
    #pragma unroll
    for (int j = 0; j < 32; j++) {
        mx0 = fmaxf(mx0, fmaxf(acc[j].x, acc[j].y));
        mx1 = fmaxf(mx1, fmaxf(acc[j].z, acc[j].w));
    }
    mx0 = fmaxf(mx0, __shfl_xor_sync(0xffffffffu, mx0, 1));
    mx0 = fmaxf(mx0, __shfl_xor_sync(0xffffffffu, mx0, 2));
    mx1 = fmaxf(mx1, __shfl_xor_sync(0xffffffffu, mx1, 1));
    mx1 = fmaxf(mx1, __shfl_xor_sync(0xffffffffu, mx1, 2));

    float sum0 = 0.0f, sum1 = 0.0f;
    #pragma unroll
    for (int j = 0; j < 32; j++) {
        float e0, e1, e2, e3;
        if (j & 1) {
            e0 = exp_poly((acc[j].x - mx0) * ATTN_SCALE);
            e1 = exp_poly((acc[j].y - mx0) * ATTN_SCALE);
            e2 = exp_poly((acc[j].z - mx1) * ATTN_SCALE);
            e3 = exp_poly((acc[j].w - mx1) * ATTN_SCALE);
        } else {
            e0 = __expf((acc[j].x - mx0) * ATTN_SCALE);
            e1 = __expf((acc[j].y - mx0) * ATTN_SCALE);
            e2 = __expf((acc[j].z - mx1) * ATTN_SCALE);
            e3 = __expf((acc[j].w - mx1) * ATTN_SCALE);
        }
        acc[j].x = e0; acc[j].y = e1; acc[j].z = e2; acc[j].w = e3;
        sum0 += e0 + e1;
        sum1 += e2 + e3;
    }
    sum0 += __shfl_xor_sync(0xffffffffu, sum0, 1);
    sum0 += __shfl_xor_sync(0xffffffffu, sum0, 2);
    sum1 += __shfl_xor_sync(0xffffffffu, sum1, 1);
    sum1 += __shfl_xor_sync(0xffffffffu, sum1, 2);
    const float inv0 = 1.0f / sum0;
    const float inv1 = 1.0f / sum1;

    {
        const int lrow0 = warp*16 + g;
        float* a0 = attnp + ((((size_t)b*NHEAD + h)*NWIN + w)*BLKT
                             + qrow0 + lrow0) * BLKT + tg*2;
        float* a1 = a0 + 8 * BLKT;
        #pragma unroll
        for (int j = 0; j < 32; j++) {
            acc[j].x *= inv0; acc[j].y *= inv0;
            acc[j].z *= inv1; acc[j].w *= inv1;
            float2 f0 = {acc[j].x, acc[j].y};
            float2 f1 = {acc[j].z, acc[j].w};
            __stcs((float2*)(a0 + j*8), f0);
            __stcs((float2*)(a1 + j*8), f1);
        }
    }

    __syncthreads();

    {
        __half* p0 = Ps + (size_t)(warp*16 + g) * PLD + tg*2;
        __half* p1 = p0 + 8 * PLD;
        #pragma unroll
        for (int j = 0; j < 32; j++) {
            *(__half2*)(p0 + j*8) = __floats2half2_rn(acc[j].x, acc[j].y);
            *(__half2*)(p1 + j*8) = __floats2half2_rn(acc[j].z, acc[j].w);
        }
    }
    __syncwarp();

    float4 oacc[8];
    #pragma unroll
    for (int t = 0; t < 8; t++) oacc[t] = make_float4(0.f, 0.f, 0.f, 0.f);

    uint32_t pbase = (uint32_t)__cvta_generic_to_shared(Ps)
                   + ((warp*16 + (lane & 15)) * PLD + ((lane & 16) ? 8 : 0)) * 2;
    uint32_t vrow = ((lane >> 3) & 1) * 8 + (lane & 7);
    uint32_t vcolh = (lane >> 4) * 8;
    uint32_t vbase = (uint32_t)__cvta_generic_to_shared(Vs)
                   + (vrow * LDH + vcolh) * 2;
    #pragma unroll
    for (int kb = 0; kb < 16; kb++) {
        uint32_t pa0, pa1, pa2, pa3;
        ldsm_x4(pa0, pa1, pa2, pa3, pbase + (uint32_t)kb * 32);
        uint32_t va = vbase + (uint32_t)(kb * 16) * LDH * 2;
        #pragma unroll
        for (int tt = 0; tt < 4; tt++) {
            uint32_t b0, b1, b2, b3;
            ldsm_x4_t(b0, b1, b2, b3, va + tt * 32);
            mma_f4(oacc[2*tt],   pa0, pa1, pa2, pa3, b0, b1);
            mma_f4(oacc[2*tt+1], pa0, pa1, pa2, pa3, b2, b3);
        }
    }

    {
        __half* orow0 = o + (tokBase + qrow0 + warp*16 + g) * DIMC + colBase + tg*2;
        __half* orow1 = orow0 + 8 * DIMC;
        #pragma unroll
        for (int t = 0; t < 8; t++) {
            *(__half2*)(orow0 + t*8) = __floats2half2_rn(oacc[t].x, oacc[t].y);
            *(__half2*)(orow1 + t*8) = __floats2half2_rn(oacc[t].z, oacc[t].w);
        }
    }
}

// ---------------------------------------------------------------------------
extern "C" void kernel_launch(void* const* d_in, const int* in_sizes, int n_in,
                              void* d_out, int out_size)
{
    const float* x  = (const float*)d_in[0];
    const float* Wq = (const float*)d_in[1];
    const float* bq = (const float*)d_in[2];
    const float* Wk = (const float*)d_in[3];
    const float* bk = (const float*)d_in[4];
    const float* Wv = (const float*)d_in[5];
    const float* bv = (const float*)d_in[6];
    const float* Wo = (const float*)d_in[7];
    const float* bo = (const float*)d_in[8];

    float* out = (float*)d_out;
    const size_t out_elems = (size_t)MTOK * DIMC;
    float* attnp = out + out_elems;

    __half* scratch = nullptr;
    cudaGetSymbolAddress((void**)&scratch, g_scratch_h);
    __half* xh  = scratch;
    __half* qh  = xh  + out_elems;
    __half* kh  = qh  + out_elems;
    __half* vh  = kh  + out_elems;
    __half* goh = vh  + out_elems;
    __half* wh  = goh + out_elems;
    const size_t wsz = (size_t)DIMC * DIMC;
    __half* whq = wh;
    __half* whk = wh + wsz;
    __half* whv = wh + 2*wsz;
    __half* who = wh + 3*wsz;

    {
        dim3 rg(256, 1, 5);
        conv_half_kernel<<<rg, 256>>>(
            (const float4*)x,  xh,
            (const float4*)Wq, whq,
            (const float4*)Wk, whk,
            (const float4*)Wv, whv,
            (const float4*)Wo, who);
    }

    const size_t gemm_smem = 2ull * 2 * BM * LDH * sizeof(__half);  // 73728
    cudaFuncSetAttribute(gemm3_f16, cudaFuncAttributeMaxDynamicSharedMemorySize, (int)gemm_smem);

    dim3 gg(DIMC / BN, MTOK / BM, 3);
    gemm3_f16<<<gg, 128, gemm_smem>>>(xh, whq, bq, qh, whk, bk, kh, whv, bv, vh, 1);

    cudaFuncSetAttribute(attn_kernel, cudaFuncAttributeMaxDynamicSharedMemorySize, ATTN_SMEM4);
    attn_kernel<<<BATCH*NHEAD*NWIN*4, 128, ATTN_SMEM4>>>(qh, kh, vh, goh, attnp);

    dim3 go_grid(DIMC / BN, MTOK / BM, 1);
    gemm3_f16<<<go_grid, 128, gemm_smem>>>(goh, who, bo, out, who, bo, out, who, bo, out, 0);
}

// round 16
// speedup vs baseline: 1.1105x; 1.0014x over previous
#include <cuda_runtime.h>
#include <cuda_fp16.h>
#include <math.h>
#include <stdint.h>

#define BATCH 4
#define SEQ   4096
#define DIMC  1024
#define NHEAD 16
#define HDIM  64
#define NWIN  16
#define BLKT  256
#define MTOK  (BATCH*SEQ)
#define ATTN_SCALE 0.125f

#define BM 128
#define BN 128
#define BKH 64
#define LDH 72           // half stride (144B rows, conflict-free LDSM)
#define NT  (DIMC / BKH)
#define PLD 264

// scratch (halves): xh, qh, kh, vh, goh (5 x 16M half) + 4 weights
__device__ __half g_scratch_h[5ull * MTOK * DIMC + 4ull * DIMC * DIMC];

// ---------------- helpers ----------------
__device__ __forceinline__ void cp_async16(void* smem, const void* gmem) {
    unsigned s = (unsigned)__cvta_generic_to_shared(smem);
    asm volatile("cp.async.cg.shared.global [%0], [%1], 16;\n" :: "r"(s), "l"(gmem));
}
__device__ __forceinline__ void cp_commit() {
    asm volatile("cp.async.commit_group;\n");
}
template<int N> __device__ __forceinline__ void cp_wait() {
    asm volatile("cp.async.wait_group %0;\n" :: "n"(N));
}
__device__ __forceinline__ float exp_poly(float v) {
    float t = v * 1.4426950408889634f;
    float fi = floorf(t);
    float f = t - fi;
    float p = 0.0001540353039338f;
    p = fmaf(p, f, 0.0013333558146428f);
    p = fmaf(p, f, 0.0096181291076285f);
    p = fmaf(p, f, 0.0555041086648216f);
    p = fmaf(p, f, 0.2402265069591007f);
    p = fmaf(p, f, 0.6931471805599453f);
    p = fmaf(p, f, 1.0f);
    int ei = (int)fi;
    ei = (ei < -126) ? -126 : ei;
    return p * __int_as_float((ei + 127) << 23);
}
__device__ __forceinline__ void ldsm_x4(uint32_t& r0, uint32_t& r1,
                                        uint32_t& r2, uint32_t& r3, uint32_t a) {
    asm volatile("ldmatrix.sync.aligned.m8n8.x4.shared.b16 {%0,%1,%2,%3}, [%4];"
                 : "=r"(r0), "=r"(r1), "=r"(r2), "=r"(r3) : "r"(a));
}
__device__ __forceinline__ void ldsm_x4_t(uint32_t& r0, uint32_t& r1,
                                          uint32_t& r2, uint32_t& r3, uint32_t a) {
    asm volatile("ldmatrix.sync.aligned.m8n8.x4.trans.shared.b16 {%0,%1,%2,%3}, [%4];"
                 : "=r"(r0), "=r"(r1), "=r"(r2), "=r"(r3) : "r"(a));
}
__device__ __forceinline__ void mma_f4(float4& c,
                                       uint32_t a0, uint32_t a1, uint32_t a2, uint32_t a3,
                                       uint32_t b0, uint32_t b1) {
    asm volatile(
        "mma.sync.aligned.m16n8k16.row.col.f32.f16.f16.f32 "
        "{%0,%1,%2,%3}, {%4,%5,%6,%7}, {%8,%9}, {%0,%1,%2,%3};"
        : "+f"(c.x), "+f"(c.y), "+f"(c.z), "+f"(c.w)
        : "r"(a0), "r"(a1), "r"(a2), "r"(a3), "r"(b0), "r"(b1));
}

// ---------------------------------------------------------------------------
// f32 -> f16 conversion prepass
// ---------------------------------------------------------------------------
__global__ void conv_half_kernel(
    const float4* __restrict__ x,  __half* __restrict__ xh,
    const float4* __restrict__ w0, __half* __restrict__ w0h,
    const float4* __restrict__ w1, __half* __restrict__ w1h,
    const float4* __restrict__ w2, __half* __restrict__ w2h,
    const float4* __restrict__ w3, __half* __restrict__ w3h)
{
    const float4* src; __half* dst; int n4;
    switch (blockIdx.z) {
        case 0:  src = x;  dst = xh;  n4 = MTOK * DIMC / 4; break;
        case 1:  src = w0; dst = w0h; n4 = DIMC * DIMC / 4; break;
        case 2:  src = w1; dst = w1h; n4 = DIMC * DIMC / 4; break;
        case 3:  src = w2; dst = w2h; n4 = DIMC * DIMC / 4; break;
        default: src = w3; dst = w3h; n4 = DIMC * DIMC / 4; break;
    }
    for (int i = blockIdx.x * blockDim.x + threadIdx.x; i < n4;
         i += gridDim.x * blockDim.x) {
        float4 v = src[i];
        __half2 a = __floats2half2_rn(v.x, v.y);
        __half2 b = __floats2half2_rn(v.z, v.w);
        uint2 o;
        o.x = *(const unsigned*)&a;
        o.y = *(const unsigned*)&b;
        *(uint2*)(dst + 4ull * i) = o;
    }
}

// ---------------------------------------------------------------------------
// fp16 GEMM v2: raw ldsm + mma (8 LDSM.x4 : 32 HMMA per kk, half the wmma
// LDSM traffic). 128x128 CTA tile, 4 warps (64x64 warp tile), BK=64, 2-stage
// cp.async wait-all pipeline, 3 CTAs/SM. Fragment mappings identical to the
// (correctness-proven) attention kernel. Epilogue writes straight from
// fragments with pre-loaded bias (no smem staging).
// ---------------------------------------------------------------------------
__global__ __launch_bounds__(128, 3) void gemm3_f16(
    const __half* __restrict__ A,
    const __half* __restrict__ W0, const float* __restrict__ b0, void* __restrict__ C0,
    const __half* __restrict__ W1, const float* __restrict__ b1, void* __restrict__ C1,
    const __half* __restrict__ W2, const float* __restrict__ b2, void* __restrict__ C2,
    int halfOut)
{
    extern __shared__ __half smh[];
    const __half* Bw; const float* bias; void* C;
    if (blockIdx.z == 0)      { Bw = W0; bias = b0; C = C0; }
    else if (blockIdx.z == 1) { Bw = W1; bias = b1; C = C1; }
    else                      { Bw = W2; bias = b2; C = C2; }

    const int K = DIMC, N = DIMC;
    const int tid  = threadIdx.x;
    const int warp = tid >> 5;
    const int lane = tid & 31;
    const int g    = lane >> 2;
    const int tg   = lane & 3;
    const int wm = warp & 1;
    const int wn = warp >> 1;
    const int rowBase = blockIdx.y * BM;
    const int colBase = blockIdx.x * BN;

    const int stageH = BM * LDH;
    auto As = [&](int s) { return smh + (size_t)s * 2 * stageH; };
    auto Bs = [&](int s) { return smh + (size_t)s * 2 * stageH + stageH; };

    const int lr = tid >> 3;
    const int lc = (tid & 7) * 8;

    auto loadStage = [&](int s, int kt) {
        __half* as = As(s); __half* bs = Bs(s);
        int k0 = kt * BKH;
        #pragma unroll
        for (int j = 0; j < 8; j++) {
            int r = lr + j * 16;
            cp_async16(&as[r * LDH + lc], &A [(size_t)(rowBase + r) * K + k0 + lc]);
            cp_async16(&bs[r * LDH + lc], &Bw[(size_t)(colBase + r) * K + k0 + lc]);
        }
        cp_commit();
    };

    // acc[i][t]: m-tile i (16 rows), n8-tile t (8 cols).
    float4 acc[4][8];
    #pragma unroll
    for (int i = 0; i < 4; i++)
        #pragma unroll
        for (int t = 0; t < 8; t++)
            acc[i][t] = make_float4(0.f, 0.f, 0.f, 0.f);

    loadStage(0, 0);

    // intra-tile fragment address offsets (bytes)
    const uint32_t aoff = ((uint32_t)(wm*64 + (lane & 15)) * LDH
                         + ((lane & 16) ? 8 : 0)) * 2;
    const uint32_t boff = ((uint32_t)(wn*64 + (lane & 7) + ((lane & 16) ? 8 : 0)) * LDH
                         + ((lane & 8) ? 8 : 0)) * 2;

    for (int kt = 0; kt < NT; kt++) {
        cp_wait<0>();
        __syncthreads();
        if (kt + 1 < NT) loadStage((kt + 1) & 1, kt + 1);

        uint32_t abase = (uint32_t)__cvta_generic_to_shared(As(kt & 1)) + aoff;
        uint32_t bbase = (uint32_t)__cvta_generic_to_shared(Bs(kt & 1)) + boff;
        #pragma unroll
        for (int kk = 0; kk < BKH; kk += 16) {
            uint32_t Bf[4][4];
            #pragma unroll
            for (int j = 0; j < 4; j++)
                ldsm_x4(Bf[j][0], Bf[j][1], Bf[j][2], Bf[j][3],
                        bbase + (uint32_t)(j*16) * LDH * 2 + kk*2);
            #pragma unroll
            for (int i = 0; i < 4; i++) {
                uint32_t a0, a1, a2, a3;
                ldsm_x4(a0, a1, a2, a3,
                        abase + (uint32_t)(i*16) * LDH * 2 + kk*2);
                #pragma unroll
                for (int j = 0; j < 4; j++) {
                    mma_f4(acc[i][2*j],   a0, a1, a2, a3, Bf[j][0], Bf[j][1]);
                    mma_f4(acc[i][2*j+1], a0, a1, a2, a3, Bf[j][2], Bf[j][3]);
                }
            }
        }
    }

    // epilogue: bias pre-load (16 values per thread), direct fragment stores
    float bv0[8], bv1[8];
    #pragma unroll
    for (int t = 0; t < 8; t++) {
        int col = colBase + wn*64 + t*8 + tg*2;
        bv0[t] = __ldg(&bias[col]);
        bv1[t] = __ldg(&bias[col + 1]);
    }
    #pragma unroll
    for (int i = 0; i < 4; i++) {
        int row0 = rowBase + wm*64 + i*16 + g;
        #pragma unroll
        for (int t = 0; t < 8; t++) {
            int col = colBase + wn*64 + t*8 + tg*2;
            float x0 = acc[i][t].x + bv0[t];
            float y0 = acc[i][t].y + bv1[t];
            float x1 = acc[i][t].z + bv0[t];
            float y1 = acc[i][t].w + bv1[t];
            if (halfOut) {
                __half* Ch = (__half*)C;
                *(__half2*)&Ch[(size_t)row0 * N + col]       = __floats2half2_rn(x0, y0);
                *(__half2*)&Ch[(size_t)(row0+8) * N + col]   = __floats2half2_rn(x1, y1);
            } else {
                float* Cf = (float*)C;
                float2 f0 = {x0, y0}, f1 = {x1, y1};
                *(float2*)&Cf[(size_t)row0 * N + col]     = f0;
                *(float2*)&Cf[(size_t)(row0+8) * N + col] = f1;
            }
        }
    }
}

// ---------------------------------------------------------------------------
// Attention v4 (unchanged from R14 best): 64 q-rows/CTA, 4 warps, 2 CTAs/SM,
// register softmax, P staged via smem aliased onto Ks.
// smem: Ks/Ps 36864 | Vs 36864 | Qs 9216 = 82944 bytes
// ---------------------------------------------------------------------------
#define ATTN_SMEM4 82944

__global__ __launch_bounds__(128, 2) void attn_kernel(
    const __half* __restrict__ q, const __half* __restrict__ k,
    const __half* __restrict__ v, __half* __restrict__ o,
    float* __restrict__ attnp)
{
    extern __shared__ char smraw[];
    __half* Ks = (__half*)smraw;
    __half* Vs = (__half*)(smraw + 36864);
    __half* Qs = (__half*)(smraw + 73728);
    __half* Ps = Ks;

    const int tid  = threadIdx.x;
    const int warp = tid >> 5;
    const int lane = tid & 31;
    const int g    = lane >> 2;
    const int tg   = lane & 3;

    const int idx  = blockIdx.x;
    const int part = idx & 3;
    const int bhw  = idx >> 2;
    const int w = bhw & 15;
    const int h = (bhw >> 4) & 15;
    const int b = bhw >> 8;

    const size_t tokBase = (size_t)b * SEQ + (size_t)w * BLKT;
    const int    colBase = h * HDIM;
    const int    qrow0   = part * 64;

    const __half* Kg = k + tokBase * DIMC + colBase;
    const __half* Vg = v + tokBase * DIMC + colBase;
    const __half* Qg = q + (tokBase + qrow0) * DIMC + colBase;

    #pragma unroll
    for (int j = 0; j < 16; j++) {
        int i = tid + j * 128;
        int r = i >> 3, u = (i & 7) * 8;
        cp_async16(&Ks[r*LDH + u], Kg + (size_t)r * DIMC + u);
        cp_async16(&Vs[r*LDH + u], Vg + (size_t)r * DIMC + u);
    }
    #pragma unroll
    for (int j = 0; j < 4; j++) {
        int i = tid + j * 128;
        int r = i >> 3, u = (i & 7) * 8;
        cp_async16(&Qs[r*LDH + u], Qg + (size_t)r * DIMC + u);
    }
    cp_commit();
    cp_wait<0>();
    __syncthreads();

    uint32_t qbase = (uint32_t)__cvta_generic_to_shared(Qs)
                   + ((warp*16 + (lane & 15)) * LDH + ((lane & 16) ? 8 : 0)) * 2;
    uint32_t Af0[4], Af1[4], Af2[4], Af3[4];
    ldsm_x4(Af0[0], Af0[1], Af0[2], Af0[3], qbase);
    ldsm_x4(Af1[0], Af1[1], Af1[2], Af1[3], qbase + 32);
    ldsm_x4(Af2[0], Af2[1], Af2[2], Af2[3], qbase + 64);
    ldsm_x4(Af3[0], Af3[1], Af3[2], Af3[3], qbase + 96);

    float4 acc[32];
    #pragma unroll
    for (int j = 0; j < 32; j++) acc[j] = make_float4(0.f, 0.f, 0.f, 0.f);

    uint32_t kbase = (uint32_t)__cvta_generic_to_shared(Ks)
                   + (((lane & 7) + ((lane & 16) ? 8 : 0)) * LDH
                      + ((lane & 8) ? 8 : 0)) * 2;
    #pragma unroll
    for (int j2 = 0; j2 < 16; j2++) {
        uint32_t kb = kbase + j2 * 16 * LDH * 2;
        uint32_t b0, b1, b2, b3;
        ldsm_x4(b0, b1, b2, b3, kb);
        mma_f4(acc[2*j2],   Af0[0], Af0[1], Af0[2], Af0[3], b0, b1);
        mma_f4(acc[2*j2+1], Af0[0], Af0[1], Af0[2], Af0[3], b2, b3);
        ldsm_x4(b0, b1, b2, b3, kb + 32);
        mma_f4(acc[2*j2],   Af1[0], Af1[1], Af1[2], Af1[3], b0, b1);
        mma_f4(acc[2*j2+1], Af1[0], Af1[1], Af1[2], Af1[3], b2, b3);
        ldsm_x4(b0, b1, b2, b3, kb + 64);
        mma_f4(acc[2*j2],   Af2[0], Af2[1], Af2[2], Af2[3], b0, b1);
        mma_f4(acc[2*j2+1], Af2[0], Af2[1], Af2[2], Af2[3], b2, b3);
        ldsm_x4(b0, b1, b2, b3, kb + 96);
        mma_f4(acc[2*j2],   Af3[0], Af3[1], Af3[2], Af3[3], b0, b1);
        mma_f4(acc[2*j2+1], Af3[0], Af3[1], Af3[2], Af3[3], b2, b3);
    }

    float mx0 = -1e30f, mx1 = -1e30f;
    #pragma unroll
    for (int j = 0; j < 32; j++) {
        mx0 = fmaxf(mx0, fmaxf(acc[j].x, acc[j].y));
        mx1 = fmaxf(mx1, fmaxf(acc[j].z, acc[j].w));
    }
    mx0 = fmaxf(mx0, __shfl_xor_sync(0xffffffffu, mx0, 1));
    mx0 = fmaxf(mx0, __shfl_xor_sync(0xffffffffu, mx0, 2));
    mx1 = fmaxf(mx1, __shfl_xor_sync(0xffffffffu, mx1, 1));
    mx1 = fmaxf(mx1, __shfl_xor_sync(0xffffffffu, mx1, 2));

    float sum0 = 0.0f, sum1 = 0.0f;
    #pragma unroll
    for (int j = 0; j < 32; j++) {
        float e0, e1, e2, e3;
        if (j & 1) {
            e0 = exp_poly((acc[j].x - mx0) * ATTN_SCALE);
            e1 = exp_poly((acc[j].y - mx0) * ATTN_SCALE);
            e2 = exp_poly((acc[j].z - mx1) * ATTN_SCALE);
            e3 = exp_poly((acc[j].w - mx1) * ATTN_SCALE);
        } else {
            e0 = __expf((acc[j].x - mx0) * ATTN_SCALE);
            e1 = __expf((acc[j].y - mx0) * ATTN_SCALE);
            e2 = __expf((acc[j].z - mx1) * ATTN_SCALE);
            e3 = __expf((acc[j].w - mx1) * ATTN_SCALE);
        }
        acc[j].x = e0; acc[j].y = e1; acc[j].z = e2; acc[j].w = e3;
        sum0 += e0 + e1;
        sum1 += e2 + e3;
    }
    sum0 += __shfl_xor_sync(0xffffffffu, sum0, 1);
    sum0 += __shfl_xor_sync(0xffffffffu, sum0, 2);
    sum1 += __shfl_xor_sync(0xffffffffu, sum1, 1);
    sum1 += __shfl_xor_sync(0xffffffffu, sum1, 2);
    const float inv0 = 1.0f / sum0;
    const float inv1 = 1.0f / sum1;

    {
        const int lrow0 = warp*16 + g;
        float* a0 = attnp + ((((size_t)b*NHEAD + h)*NWIN + w)*BLKT
                             + qrow0 + lrow0) * BLKT + tg*2;
        float* a1 = a0 + 8 * BLKT;
        #pragma unroll
        for (int j = 0; j < 32; j++) {
            acc[j].x *= inv0; acc[j].y *= inv0;
            acc[j].z *= inv1; acc[j].w *= inv1;
            float2 f0 = {acc[j].x, acc[j].y};
            float2 f1 = {acc[j].z, acc[j].w};
            __stcs((float2*)(a0 + j*8), f0);
            __stcs((float2*)(a1 + j*8), f1);
        }
    }

    __syncthreads();

    {
        __half* p0 = Ps + (size_t)(warp*16 + g) * PLD + tg*2;
        __half* p1 = p0 + 8 * PLD;
        #pragma unroll
        for (int j = 0; j < 32; j++) {
            *(__half2*)(p0 + j*8) = __floats2half2_rn(acc[j].x, acc[j].y);
            *(__half2*)(p1 + j*8) = __floats2half2_rn(acc[j].z, acc[j].w);
        }
    }
    __syncwarp();

    float4 oacc[8];
    #pragma unroll
    for (int t = 0; t < 8; t++) oacc[t] = make_float4(0.f, 0.f, 0.f, 0.f);

    uint32_t pbase = (uint32_t)__cvta_generic_to_shared(Ps)
                   + ((warp*16 + (lane & 15)) * PLD + ((lane & 16) ? 8 : 0)) * 2;
    uint32_t vrow = ((lane >> 3) & 1) * 8 + (lane & 7);
    uint32_t vcolh = (lane >> 4) * 8;
    uint32_t vbase = (uint32_t)__cvta_generic_to_shared(Vs)
                   + (vrow * LDH + vcolh) * 2;
    #pragma unroll
    for (int kb = 0; kb < 16; kb++) {
        uint32_t pa0, pa1, pa2, pa3;
        ldsm_x4(pa0, pa1, pa2, pa3, pbase + (uint32_t)kb * 32);
        uint32_t va = vbase + (uint32_t)(kb * 16) * LDH * 2;
        #pragma unroll
        for (int tt = 0; tt < 4; tt++) {
            uint32_t b0, b1, b2, b3;
            ldsm_x4_t(b0, b1, b2, b3, va + tt * 32);
            mma_f4(oacc[2*tt],   pa0, pa1, pa2, pa3, b0, b1);
            mma_f4(oacc[2*tt+1], pa0, pa1, pa2, pa3, b2, b3);
        }
    }

    {
        __half* orow0 = o + (tokBase + qrow0 + warp*16 + g) * DIMC + colBase + tg*2;
        __half* orow1 = orow0 + 8 * DIMC;
        #pragma unroll
        for (int t = 0; t < 8; t++) {
            *(__half2*)(orow0 + t*8) = __floats2half2_rn(oacc[t].x, oacc[t].y);
            *(__half2*)(orow1 + t*8) = __floats2half2_rn(oacc[t].z, oacc[t].w);
        }
    }
}

// ---------------------------------------------------------------------------
extern "C" void kernel_launch(void* const* d_in, const int* in_sizes, int n_in,
                              void* d_out, int out_size)
{
    const float* x  = (const float*)d_in[0];
    const float* Wq = (const float*)d_in[1];
    const float* bq = (const float*)d_in[2];
    const float* Wk = (const float*)d_in[3];
    const float* bk = (const float*)d_in[4];
    const float* Wv = (const float*)d_in[5];
    const float* bv = (const float*)d_in[6];
    const float* Wo = (const float*)d_in[7];
    const float* bo = (const float*)d_in[8];

    float* out = (float*)d_out;
    const size_t out_elems = (size_t)MTOK * DIMC;
    float* attnp = out + out_elems;

    __half* scratch = nullptr;
    cudaGetSymbolAddress((void**)&scratch, g_scratch_h);
    __half* xh  = scratch;
    __half* qh  = xh  + out_elems;
    __half* kh  = qh  + out_elems;
    __half* vh  = kh  + out_elems;
    __half* goh = vh  + out_elems;
    __half* wh  = goh + out_elems;
    const size_t wsz = (size_t)DIMC * DIMC;
    __half* whq = wh;
    __half* whk = wh + wsz;
    __half* whv = wh + 2*wsz;
    __half* who = wh + 3*wsz;

    {
        dim3 rg(256, 1, 5);
        conv_half_kernel<<<rg, 256>>>(
            (const float4*)x,  xh,
            (const float4*)Wq, whq,
            (const float4*)Wk, whk,
            (const float4*)Wv, whv,
            (const float4*)Wo, who);
    }

    const size_t gemm_smem = 2ull * 2 * BM * LDH * sizeof(__half);  // 73728
    cudaFuncSetAttribute(gemm3_f16, cudaFuncAttributeMaxDynamicSharedMemorySize, (int)gemm_smem);

    dim3 gg(DIMC / BN, MTOK / BM, 3);
    gemm3_f16<<<gg, 128, gemm_smem>>>(xh, whq, bq, qh, whk, bk, kh, whv, bv, vh, 1);

    cudaFuncSetAttribute(attn_kernel, cudaFuncAttributeMaxDynamicSharedMemorySize, ATTN_SMEM4);
    attn_kernel<<<BATCH*NHEAD*NWIN*4, 128, ATTN_SMEM4>>>(qh, kh, vh, goh, attnp);

    dim3 go_grid(DIMC / BN, MTOK / BM, 1);
    gemm3_f16<<<go_grid, 128, gemm_smem>>>(goh, who, bo, out, who, bo, out, who, bo, out, 0);
}

// round 17
// speedup vs baseline: 1.1115x; 1.0010x over previous
#include <cuda_runtime.h>
#include <cuda_fp16.h>
#include <math.h>
#include <stdint.h>

#define BATCH 4
#define SEQ   4096
#define DIMC  1024
#define NHEAD 16
#define HDIM  64
#define NWIN  16
#define BLKT  256
#define MTOK  (BATCH*SEQ)
#define ATTN_SCALE 0.125f

#define GBM 192          // GEMM CTA tile M (3 m-warps x 64)
#define GBN 128          // GEMM CTA tile N (2 n-warps x 64)
#define BKH 64
#define LDH 72           // half stride (144B rows, conflict-free LDSM)
#define NT  (DIMC / BKH)
#define PLD 264

// scratch (halves): xh, qh, kh, vh, goh (5 x 16M half) + 4 weights
__device__ __half g_scratch_h[5ull * MTOK * DIMC + 4ull * DIMC * DIMC];

// ---------------- helpers ----------------
__device__ __forceinline__ void cp_async16(void* smem, const void* gmem) {
    unsigned s = (unsigned)__cvta_generic_to_shared(smem);
    asm volatile("cp.async.cg.shared.global [%0], [%1], 16;\n" :: "r"(s), "l"(gmem));
}
__device__ __forceinline__ void cp_commit() {
    asm volatile("cp.async.commit_group;\n");
}
template<int N> __device__ __forceinline__ void cp_wait() {
    asm volatile("cp.async.wait_group %0;\n" :: "n"(N));
}
__device__ __forceinline__ float exp_poly(float v) {
    float t = v * 1.4426950408889634f;
    float fi = floorf(t);
    float f = t - fi;
    float p = 0.0001540353039338f;
    p = fmaf(p, f, 0.0013333558146428f);
    p = fmaf(p, f, 0.0096181291076285f);
    p = fmaf(p, f, 0.0555041086648216f);
    p = fmaf(p, f, 0.2402265069591007f);
    p = fmaf(p, f, 0.6931471805599453f);
    p = fmaf(p, f, 1.0f);
    int ei = (int)fi;
    ei = (ei < -126) ? -126 : ei;
    return p * __int_as_float((ei + 127) << 23);
}
__device__ __forceinline__ void ldsm_x4(uint32_t& r0, uint32_t& r1,
                                        uint32_t& r2, uint32_t& r3, uint32_t a) {
    asm volatile("ldmatrix.sync.aligned.m8n8.x4.shared.b16 {%0,%1,%2,%3}, [%4];"
                 : "=r"(r0), "=r"(r1), "=r"(r2), "=r"(r3) : "r"(a));
}
__device__ __forceinline__ void ldsm_x4_t(uint32_t& r0, uint32_t& r1,
                                          uint32_t& r2, uint32_t& r3, uint32_t a) {
    asm volatile("ldmatrix.sync.aligned.m8n8.x4.trans.shared.b16 {%0,%1,%2,%3}, [%4];"
                 : "=r"(r0), "=r"(r1), "=r"(r2), "=r"(r3) : "r"(a));
}
__device__ __forceinline__ void mma_f4(float4& c,
                                       uint32_t a0, uint32_t a1, uint32_t a2, uint32_t a3,
                                       uint32_t b0, uint32_t b1) {
    asm volatile(
        "mma.sync.aligned.m16n8k16.row.col.f32.f16.f16.f32 "
        "{%0,%1,%2,%3}, {%4,%5,%6,%7}, {%8,%9}, {%0,%1,%2,%3};"
        : "+f"(c.x), "+f"(c.y), "+f"(c.z), "+f"(c.w)
        : "r"(a0), "r"(a1), "r"(a2), "r"(a3), "r"(b0), "r"(b1));
}

// ---------------------------------------------------------------------------
// f32 -> f16 conversion prepass (wider grid: 1 grid-stride iter per tensor)
// ---------------------------------------------------------------------------
__global__ void conv_half_kernel(
    const float4* __restrict__ x,  __half* __restrict__ xh,
    const float4* __restrict__ w0, __half* __restrict__ w0h,
    const float4* __restrict__ w1, __half* __restrict__ w1h,
    const float4* __restrict__ w2, __half* __restrict__ w2h,
    const float4* __restrict__ w3, __half* __restrict__ w3h)
{
    const float4* src; __half* dst; int n4;
    switch (blockIdx.z) {
        case 0:  src = x;  dst = xh;  n4 = MTOK * DIMC / 4; break;
        case 1:  src = w0; dst = w0h; n4 = DIMC * DIMC / 4; break;
        case 2:  src = w1; dst = w1h; n4 = DIMC * DIMC / 4; break;
        case 3:  src = w2; dst = w2h; n4 = DIMC * DIMC / 4; break;
        default: src = w3; dst = w3h; n4 = DIMC * DIMC / 4; break;
    }
    for (int i = blockIdx.x * blockDim.x + threadIdx.x; i < n4;
         i += gridDim.x * blockDim.x) {
        float4 v = src[i];
        __half2 a = __floats2half2_rn(v.x, v.y);
        __half2 b = __floats2half2_rn(v.z, v.w);
        uint2 o;
        o.x = *(const unsigned*)&a;
        o.y = *(const unsigned*)&b;
        *(uint2*)(dst + 4ull * i) = o;
    }
}

// ---------------------------------------------------------------------------
// fp16 GEMM v3: 192x128 CTA tile (intensity 76.8 FLOP/B vs 57 at 128x128 --
// the kernel is L2-BW bound), 6 warps (3x2 of 64x64), raw ldsm+mma, BK=64,
// 2-stage cp.async wait-all pipeline, 2 CTAs/SM (12 warps).
// M=16384 not divisible by 192 -> grid.y=86, store guards (overreads land
// inside g_scratch; loads always legal).
// ---------------------------------------------------------------------------
__global__ __launch_bounds__(192, 2) void gemm3_f16(
    const __half* __restrict__ A,
    const __half* __restrict__ W0, const float* __restrict__ b0, void* __restrict__ C0,
    const __half* __restrict__ W1, const float* __restrict__ b1, void* __restrict__ C1,
    const __half* __restrict__ W2, const float* __restrict__ b2, void* __restrict__ C2,
    int halfOut)
{
    extern __shared__ __half smh[];
    const __half* Bw; const float* bias; void* C;
    if (blockIdx.z == 0)      { Bw = W0; bias = b0; C = C0; }
    else if (blockIdx.z == 1) { Bw = W1; bias = b1; C = C1; }
    else                      { Bw = W2; bias = b2; C = C2; }

    const int K = DIMC, N = DIMC;
    const int tid  = threadIdx.x;
    const int warp = tid >> 5;          // 0..5
    const int lane = tid & 31;
    const int g    = lane >> 2;
    const int tg   = lane & 3;
    const int wm = warp % 3;            // 3 m-warps
    const int wn = warp / 3;            // 2 n-warps
    const int rowBase = blockIdx.y * GBM;
    const int colBase = blockIdx.x * GBN;

    const int stageH = (GBM + GBN) * LDH;      // halves per stage
    auto As = [&](int s) { return smh + (size_t)s * stageH; };
    auto Bs = [&](int s) { return smh + (size_t)s * stageH + GBM * LDH; };

    auto loadStage = [&](int s, int kt) {
        __half* as = As(s); __half* bs = Bs(s);
        int k0 = kt * BKH;
        // A: 192 rows x 8 chunks = 1536 (8 iters exact at 192 threads)
        #pragma unroll
        for (int j = 0; j < 8; j++) {
            int c = tid + j * 192;
            int r = c >> 3, u = (c & 7) * 8;
            cp_async16(&as[r * LDH + u], &A[(size_t)(rowBase + r) * K + k0 + u]);
        }
        // B: 128 rows x 8 chunks = 1024 (5 full iters + partial)
        #pragma unroll
        for (int j = 0; j < 6; j++) {
            int c = tid + j * 192;
            if (c < 1024) {
                int r = c >> 3, u = (c & 7) * 8;
                cp_async16(&bs[r * LDH + u], &Bw[(size_t)(colBase + r) * K + k0 + u]);
            }
        }
        cp_commit();
    };

    float4 acc[4][8];
    #pragma unroll
    for (int i = 0; i < 4; i++)
        #pragma unroll
        for (int t = 0; t < 8; t++)
            acc[i][t] = make_float4(0.f, 0.f, 0.f, 0.f);

    loadStage(0, 0);

    const uint32_t aoff = ((uint32_t)(wm*64 + (lane & 15)) * LDH
                         + ((lane & 16) ? 8 : 0)) * 2;
    const uint32_t boff = ((uint32_t)(wn*64 + (lane & 7) + ((lane & 16) ? 8 : 0)) * LDH
                         + ((lane & 8) ? 8 : 0)) * 2;

    for (int kt = 0; kt < NT; kt++) {
        cp_wait<0>();
        __syncthreads();
        if (kt + 1 < NT) loadStage((kt + 1) & 1, kt + 1);

        uint32_t abase = (uint32_t)__cvta_generic_to_shared(As(kt & 1)) + aoff;
        uint32_t bbase = (uint32_t)__cvta_generic_to_shared(Bs(kt & 1)) + boff;
        #pragma unroll
        for (int kk = 0; kk < BKH; kk += 16) {
            uint32_t Bf[4][4];
            #pragma unroll
            for (int j = 0; j < 4; j++)
                ldsm_x4(Bf[j][0], Bf[j][1], Bf[j][2], Bf[j][3],
                        bbase + (uint32_t)(j*16) * LDH * 2 + kk*2);
            #pragma unroll
            for (int i = 0; i < 4; i++) {
                uint32_t a0, a1, a2, a3;
                ldsm_x4(a0, a1, a2, a3,
                        abase + (uint32_t)(i*16) * LDH * 2 + kk*2);
                #pragma unroll
                for (int j = 0; j < 4; j++) {
                    mma_f4(acc[i][2*j],   a0, a1, a2, a3, Bf[j][0], Bf[j][1]);
                    mma_f4(acc[i][2*j+1], a0, a1, a2, a3, Bf[j][2], Bf[j][3]);
                }
            }
        }
    }

    // epilogue: bias pre-load, direct fragment stores, row guards
    float bv0[8], bv1[8];
    #pragma unroll
    for (int t = 0; t < 8; t++) {
        int col = colBase + wn*64 + t*8 + tg*2;
        bv0[t] = __ldg(&bias[col]);
        bv1[t] = __ldg(&bias[col + 1]);
    }
    #pragma unroll
    for (int i = 0; i < 4; i++) {
        int row0 = rowBase + wm*64 + i*16 + g;
        bool ok0 = row0 < MTOK;
        bool ok1 = (row0 + 8) < MTOK;
        #pragma unroll
        for (int t = 0; t < 8; t++) {
            int col = colBase + wn*64 + t*8 + tg*2;
            float x0 = acc[i][t].x + bv0[t];
            float y0 = acc[i][t].y + bv1[t];
            float x1 = acc[i][t].z + bv0[t];
            float y1 = acc[i][t].w + bv1[t];
            if (halfOut) {
                __half* Ch = (__half*)C;
                if (ok0) *(__half2*)&Ch[(size_t)row0 * N + col]     = __floats2half2_rn(x0, y0);
                if (ok1) *(__half2*)&Ch[(size_t)(row0+8) * N + col] = __floats2half2_rn(x1, y1);
            } else {
                float* Cf = (float*)C;
                float2 f0 = {x0, y0}, f1 = {x1, y1};
                if (ok0) *(float2*)&Cf[(size_t)row0 * N + col]     = f0;
                if (ok1) *(float2*)&Cf[(size_t)(row0+8) * N + col] = f1;
            }
        }
    }
}

// ---------------------------------------------------------------------------
// Attention v4 (unchanged, ~66us): 64 q-rows/CTA, 4 warps, 2 CTAs/SM.
// smem: Ks/Ps 36864 | Vs 36864 | Qs 9216 = 82944 bytes
// ---------------------------------------------------------------------------
#define ATTN_SMEM4 82944

__global__ __launch_bounds__(128, 2) void attn_kernel(
    const __half* __restrict__ q, const __half* __restrict__ k,
    const __half* __restrict__ v, __half* __restrict__ o,
    float* __restrict__ attnp)
{
    extern __shared__ char smraw[];
    __half* Ks = (__half*)smraw;
    __half* Vs = (__half*)(smraw + 36864);
    __half* Qs = (__half*)(smraw + 73728);
    __half* Ps = Ks;

    const int tid  = threadIdx.x;
    const int warp = tid >> 5;
    const int lane = tid & 31;
    const int g    = lane >> 2;
    const int tg   = lane & 3;

    const int idx  = blockIdx.x;
    const int part = idx & 3;
    const int bhw  = idx >> 2;
    const int w = bhw & 15;
    const int h = (bhw >> 4) & 15;
    const int b = bhw >> 8;

    const size_t tokBase = (size_t)b * SEQ + (size_t)w * BLKT;
    const int    colBase = h * HDIM;
    const int    qrow0   = part * 64;

    const __half* Kg = k + tokBase * DIMC + colBase;
    const __half* Vg = v + tokBase * DIMC + colBase;
    const __half* Qg = q + (tokBase + qrow0) * DIMC + colBase;

    #pragma unroll
    for (int j = 0; j < 16; j++) {
        int i = tid + j * 128;
        int r = i >> 3, u = (i & 7) * 8;
        cp_async16(&Ks[r*LDH + u], Kg + (size_t)r * DIMC + u);
        cp_async16(&Vs[r*LDH + u], Vg + (size_t)r * DIMC + u);
    }
    #pragma unroll
    for (int j = 0; j < 4; j++) {
        int i = tid + j * 128;
        int r = i >> 3, u = (i & 7) * 8;
        cp_async16(&Qs[r*LDH + u], Qg + (size_t)r * DIMC + u);
    }
    cp_commit();
    cp_wait<0>();
    __syncthreads();

    uint32_t qbase = (uint32_t)__cvta_generic_to_shared(Qs)
                   + ((warp*16 + (lane & 15)) * LDH + ((lane & 16) ? 8 : 0)) * 2;
    uint32_t Af0[4], Af1[4], Af2[4], Af3[4];
    ldsm_x4(Af0[0], Af0[1], Af0[2], Af0[3], qbase);
    ldsm_x4(Af1[0], Af1[1], Af1[2], Af1[3], qbase + 32);
    ldsm_x4(Af2[0], Af2[1], Af2[2], Af2[3], qbase + 64);
    ldsm_x4(Af3[0], Af3[1], Af3[2], Af3[3], qbase + 96);

    float4 acc[32];
    #pragma unroll
    for (int j = 0; j < 32; j++) acc[j] = make_float4(0.f, 0.f, 0.f, 0.f);

    uint32_t kbase = (uint32_t)__cvta_generic_to_shared(Ks)
                   + (((lane & 7) + ((lane & 16) ? 8 : 0)) * LDH
                      + ((lane & 8) ? 8 : 0)) * 2;
    #pragma unroll
    for (int j2 = 0; j2 < 16; j2++) {
        uint32_t kb = kbase + j2 * 16 * LDH * 2;
        uint32_t b0, b1, b2, b3;
        ldsm_x4(b0, b1, b2, b3, kb);
        mma_f4(acc[2*j2],   Af0[0], Af0[1], Af0[2], Af0[3], b0, b1);
        mma_f4(acc[2*j2+1], Af0[0], Af0[1], Af0[2], Af0[3], b2, b3);
        ldsm_x4(b0, b1, b2, b3, kb + 32);
        mma_f4(acc[2*j2],   Af1[0], Af1[1], Af1[2], Af1[3], b0, b1);
        mma_f4(acc[2*j2+1], Af1[0], Af1[1], Af1[2], Af1[3], b2, b3);
        ldsm_x4(b0, b1, b2, b3, kb + 64);
        mma_f4(acc[2*j2],   Af2[0], Af2[1], Af2[2], Af2[3], b0, b1);
        mma_f4(acc[2*j2+1], Af2[0], Af2[1], Af2[2], Af2[3], b2, b3);
        ldsm_x4(b0, b1, b2, b3, kb + 96);
        mma_f4(acc[2*j2],   Af3[0], Af3[1], Af3[2], Af3[3], b0, b1);
        mma_f4(acc[2*j2+1], Af3[0], Af3[1], Af3[2], Af3[3], b2, b3);
    }

    float mx0 = -1e30f, mx1 = -1e30f;
    #pragma unroll
    for (int j = 0; j < 32; j++) {
        mx0 = fmaxf(mx0, fmaxf(acc[j].x, acc[j].y));
        mx1 = fmaxf(mx1, fmaxf(acc[j].z, acc[j].w));
    }
    mx0 = fmaxf(mx0, __shfl_xor_sync(0xffffffffu, mx0, 1));
    mx0 = fmaxf(mx0, __shfl_xor_sync(0xffffffffu, mx0, 2));
    mx1 = fmaxf(mx1, __shfl_xor_sync(0xffffffffu, mx1, 1));
    mx1 = fmaxf(mx1, __shfl_xor_sync(0xffffffffu, mx1, 2));

    float sum0 = 0.0f, sum1 = 0.0f;
    #pragma unroll
    for (int j = 0; j < 32; j++) {
        float e0, e1, e2, e3;
        if (j & 1) {
            e0 = exp_poly((acc[j].x - mx0) * ATTN_SCALE);
            e1 = exp_poly((acc[j].y - mx0) * ATTN_SCALE);
            e2 = exp_poly((acc[j].z - mx1) * ATTN_SCALE);
            e3 = exp_poly((acc[j].w - mx1) * ATTN_SCALE);
        } else {
            e0 = __expf((acc[j].x - mx0) * ATTN_SCALE);
            e1 = __expf((acc[j].y - mx0) * ATTN_SCALE);
            e2 = __expf((acc[j].z - mx1) * ATTN_SCALE);
            e3 = __expf((acc[j].w - mx1) * ATTN_SCALE);
        }
        acc[j].x = e0; acc[j].y = e1; acc[j].z = e2; acc[j].w = e3;
        sum0 += e0 + e1;
        sum1 += e2 + e3;
    }
    sum0 += __shfl_xor_sync(0xffffffffu, sum0, 1);
    sum0 += __shfl_xor_sync(0xffffffffu, sum0, 2);
    sum1 += __shfl_xor_sync(0xffffffffu, sum1, 1);
    sum1 += __shfl_xor_sync(0xffffffffu, sum1, 2);
    const float inv0 = 1.0f / sum0;
    const float inv1 = 1.0f / sum1;

    {
        const int lrow0 = warp*16 + g;
        float* a0 = attnp + ((((size_t)b*NHEAD + h)*NWIN + w)*BLKT
                             + qrow0 + lrow0) * BLKT + tg*2;
        float* a1 = a0 + 8 * BLKT;
        #pragma unroll
        for (int j = 0; j < 32; j++) {
            acc[j].x *= inv0; acc[j].y *= inv0;
            acc[j].z *= inv1; acc[j].w *= inv1;
            float2 f0 = {acc[j].x, acc[j].y};
            float2 f1 = {acc[j].z, acc[j].w};
            __stcs((float2*)(a0 + j*8), f0);
            __stcs((float2*)(a1 + j*8), f1);
        }
    }

    __syncthreads();

    {
        __half* p0 = Ps + (size_t)(warp*16 + g) * PLD + tg*2;
        __half* p1 = p0 + 8 * PLD;
        #pragma unroll
        for (int j = 0; j < 32; j++) {
            *(__half2*)(p0 + j*8) = __floats2half2_rn(acc[j].x, acc[j].y);
            *(__half2*)(p1 + j*8) = __floats2half2_rn(acc[j].z, acc[j].w);
        }
    }
    __syncwarp();

    float4 oacc[8];
    #pragma unroll
    for (int t = 0; t < 8; t++) oacc[t] = make_float4(0.f, 0.f, 0.f, 0.f);

    uint32_t pbase = (uint32_t)__cvta_generic_to_shared(Ps)
                   + ((warp*16 + (lane & 15)) * PLD + ((lane & 16) ? 8 : 0)) * 2;
    uint32_t vrow = ((lane >> 3) & 1) * 8 + (lane & 7);
    uint32_t vcolh = (lane >> 4) * 8;
    uint32_t vbase = (uint32_t)__cvta_generic_to_shared(Vs)
                   + (vrow * LDH + vcolh) * 2;
    #pragma unroll
    for (int kb = 0; kb < 16; kb++) {
        uint32_t pa0, pa1, pa2, pa3;
        ldsm_x4(pa0, pa1, pa2, pa3, pbase + (uint32_t)kb * 32);
        uint32_t va = vbase + (uint32_t)(kb * 16) * LDH * 2;
        #pragma unroll
        for (int tt = 0; tt < 4; tt++) {
            uint32_t b0, b1, b2, b3;
            ldsm_x4_t(b0, b1, b2, b3, va + tt * 32);
            mma_f4(oacc[2*tt],   pa0, pa1, pa2, pa3, b0, b1);
            mma_f4(oacc[2*tt+1], pa0, pa1, pa2, pa3, b2, b3);
        }
    }

    {
        __half* orow0 = o + (tokBase + qrow0 + warp*16 + g) * DIMC + colBase + tg*2;
        __half* orow1 = orow0 + 8 * DIMC;
        #pragma unroll
        for (int t = 0; t < 8; t++) {
            *(__half2*)(orow0 + t*8) = __floats2half2_rn(oacc[t].x, oacc[t].y);
            *(__half2*)(orow1 + t*8) = __floats2half2_rn(oacc[t].z, oacc[t].w);
        }
    }
}

// ---------------------------------------------------------------------------
extern "C" void kernel_launch(void* const* d_in, const int* in_sizes, int n_in,
                              void* d_out, int out_size)
{
    const float* x  = (const float*)d_in[0];
    const float* Wq = (const float*)d_in[1];
    const float* bq = (const float*)d_in[2];
    const float* Wk = (const float*)d_in[3];
    const float* bk = (const float*)d_in[4];
    const float* Wv = (const float*)d_in[5];
    const float* bv = (const float*)d_in[6];
    const float* Wo = (const float*)d_in[7];
    const float* bo = (const float*)d_in[8];

    float* out = (float*)d_out;
    const size_t out_elems = (size_t)MTOK * DIMC;
    float* attnp = out + out_elems;

    __half* scratch = nullptr;
    cudaGetSymbolAddress((void**)&scratch, g_scratch_h);
    __half* xh  = scratch;
    __half* qh  = xh  + out_elems;
    __half* kh  = qh  + out_elems;
    __half* vh  = kh  + out_elems;
    __half* goh = vh  + out_elems;
    __half* wh  = goh + out_elems;
    const size_t wsz = (size_t)DIMC * DIMC;
    __half* whq = wh;
    __half* whk = wh + wsz;
    __half* whv = wh + 2*wsz;
    __half* who = wh + 3*wsz;

    {
        dim3 rg(1024, 1, 5);
        conv_half_kernel<<<rg, 256>>>(
            (const float4*)x,  xh,
            (const float4*)Wq, whq,
            (const float4*)Wk, whk,
            (const float4*)Wv, whv,
            (const float4*)Wo, who);
    }

    const size_t gemm_smem = 2ull * (GBM + GBN) * LDH * sizeof(__half);  // 92160
    cudaFuncSetAttribute(gemm3_f16, cudaFuncAttributeMaxDynamicSharedMemorySize, (int)gemm_smem);

    const int gy = (MTOK + GBM - 1) / GBM;     // 86
    dim3 gg(DIMC / GBN, gy, 3);
    gemm3_f16<<<gg, 192, gemm_smem>>>(xh, whq, bq, qh, whk, bk, kh, whv, bv, vh, 1);

    cudaFuncSetAttribute(attn_kernel, cudaFuncAttributeMaxDynamicSharedMemorySize, ATTN_SMEM4);
    attn_kernel<<<BATCH*NHEAD*NWIN*4, 128, ATTN_SMEM4>>>(qh, kh, vh, goh, attnp);

    dim3 go_grid(DIMC / GBN, gy, 1);
    gemm3_f16<<<go_grid, 192, gemm_smem>>>(goh, who, bo, out, who, bo, out, who, bo, out, 0);
}